// round 13
// baseline (speedup 1.0000x reference)
#include <cuda_runtime.h>
#include <cuda_bf16.h>
#include <math.h>
#include <stdint.h>

// ---------------- problem constants ----------------
#define Bq   8
#define SPq  800
#define SSq  48
#define NTq  848
#define DPq  2048
#define DSq  1024
#define DCq  1024
#define Hq   8
#define HDq  256
#define FPq  16384
#define FSq  4096
#define EPSq 1e-6f
#define MASKV (-2.3819763e+38f)
#define NQKV 2560                 // fused QKV output cols (2048 q + 256 k + 256 v)

static constexpr size_t NPROW = (size_t)Bq * SPq;   // 6400
static constexpr size_t NSROW = (size_t)Bq * SSq;   // 384

// ---------------- f32 scratch ----------------
static constexpr size_t O_MOD1 = 0;
static constexpr size_t O_MOD2 = O_MOD1 + (size_t)Bq * 3 * DSq;
static constexpr size_t O_QKVP = O_MOD2 + (size_t)Bq * 3 * DSq;           // [6400,2560]
static constexpr size_t O_QKVS = O_QKVP + NPROW * (size_t)NQKV;           // [384,2560]
static constexpr size_t O_SCF  = O_QKVS + NSROW * (size_t)NQKV;           // scores f32
static constexpr size_t O_UPF  = O_SCF  + (size_t)Bq*Hq*NTq*NTq;
static constexpr size_t O_USF  = O_UPF  + NPROW * FPq;
static constexpr size_t O_RESP = O_USF  + NSROW * FSq;
static constexpr size_t O_RESS = O_RESP + NPROW * DPq;
static constexpr size_t F32_TOTAL = O_RESS + NSROW * DSq;

__device__ float g_scr[F32_TOTAL];

// ---------------- bf16 scratch (hi set + lo set) ----------------
static constexpr size_t B_HP   = 0;
static constexpr size_t B_HS   = B_HP  + NPROW * DPq;
static constexpr size_t B_Q    = B_HS  + NSROW * DSq;
static constexpr size_t B_K    = B_Q   + (size_t)Bq*Hq*NTq*HDq;
static constexpr size_t B_VT   = B_K   + (size_t)Bq*NTq*HDq;
static constexpr size_t B_SC   = B_VT  + (size_t)Bq*NTq*HDq;
static constexpr size_t B_AP   = B_SC  + (size_t)Bq*Hq*NTq*NTq;
static constexpr size_t B_AS   = B_AP  + NPROW * (size_t)(Hq*HDq);
static constexpr size_t B_HP2  = B_AS  + NSROW * (size_t)(Hq*HDq);
static constexpr size_t B_HPM  = B_HP2 + NPROW * DPq;
static constexpr size_t B_H2S  = B_HPM + NPROW * FPq;
static constexpr size_t B_HSM  = B_H2S + NSROW * DSq;
static constexpr size_t B_WPQ  = B_HSM + NSROW * FSq;                     // Wq|Wk|Wv contiguous
static constexpr size_t B_WPK  = B_WPQ + (size_t)(Hq*HDq)*DPq;
static constexpr size_t B_WPV  = B_WPK + (size_t)HDq*DPq;
static constexpr size_t B_WPO  = B_WPV + (size_t)HDq*DPq;
static constexpr size_t B_WPG  = B_WPO + (size_t)DPq*(Hq*HDq);
static constexpr size_t B_WPU  = B_WPG + (size_t)FPq*DPq;
static constexpr size_t B_WPD  = B_WPU + (size_t)FPq*DPq;
static constexpr size_t B_WSQ  = B_WPD + (size_t)DPq*FPq;                 // Wq|Wk|Wv contiguous
static constexpr size_t B_WSK  = B_WSQ + (size_t)(Hq*HDq)*DSq;
static constexpr size_t B_WSV  = B_WSK + (size_t)HDq*DSq;
static constexpr size_t B_WSO  = B_WSV + (size_t)HDq*DSq;
static constexpr size_t B_WSG  = B_WSO + (size_t)DSq*(Hq*HDq);
static constexpr size_t B_WSU  = B_WSG + (size_t)FSq*DSq;
static constexpr size_t B_WSD  = B_WSU + (size_t)FSq*DSq;
static constexpr size_t SET_TOTAL = B_WSD + (size_t)DSq*FSq;

__device__ __nv_bfloat16 g_scrh[2 * SET_TOTAL];

// ---------------- helpers ----------------
__device__ __forceinline__ uint32_t smem_u32(const void* p) {
    uint32_t a;
    asm("{ .reg .u64 t; cvta.to.shared.u64 t, %1; cvt.u32.u64 %0, t; }" : "=r"(a) : "l"(p));
    return a;
}
#define LDM_X4(R, addr) \
    asm volatile("ldmatrix.sync.aligned.m8n8.x4.shared.b16 {%0,%1,%2,%3}, [%4];" \
        : "=r"((R)[0]), "=r"((R)[1]), "=r"((R)[2]), "=r"((R)[3]) : "r"(addr))
#define CP_A16(dst, src, sz) \
    asm volatile("cp.async.cg.shared.global [%0], [%1], 16, %2;" \
        :: "r"(dst), "l"(src), "r"(sz) : "memory")
#define CP_COMMIT() asm volatile("cp.async.commit_group;" ::: "memory")
#define CP_WAIT1()  asm volatile("cp.async.wait_group 1;" ::: "memory")

__device__ __forceinline__ float gelu_tanh(float x) {
    float x3 = x * x * x;
    return 0.5f * x * (1.0f + tanhf(0.7978845608028654f * (x + 0.044715f * x3)));
}
__device__ __forceinline__ void split2(float x, float y, uint32_t& hi, uint32_t& lo) {
    __nv_bfloat16 hx = __float2bfloat16_rn(x);
    __nv_bfloat16 hy = __float2bfloat16_rn(y);
    float rx = x - __bfloat162float(hx);
    float ry = y - __bfloat162float(hy);
    __nv_bfloat16 lx = __float2bfloat16_rn(rx);
    __nv_bfloat16 ly = __float2bfloat16_rn(ry);
    hi = (uint32_t)__bfloat16_as_ushort(hx) | ((uint32_t)__bfloat16_as_ushort(hy) << 16);
    lo = (uint32_t)__bfloat16_as_ushort(lx) | ((uint32_t)__bfloat16_as_ushort(ly) << 16);
}
__device__ __forceinline__ void emit1(__nv_bfloat16* h, __nv_bfloat16* l, size_t off, float v) {
    __nv_bfloat16 hv = __float2bfloat16_rn(v);
    h[off] = hv;
    l[off] = __float2bfloat16_rn(v - __bfloat162float(hv));
}

#define MMA_BF16(d, a, b) \
    asm volatile("mma.sync.aligned.m16n8k16.row.col.f32.bf16.bf16.f32 " \
        "{%0,%1,%2,%3}, {%4,%5,%6,%7}, {%8,%9}, {%0,%1,%2,%3};" \
        : "+f"((d)[0]), "+f"((d)[1]), "+f"((d)[2]), "+f"((d)[3]) \
        : "r"((a)[0]), "r"((a)[1]), "r"((a)[2]), "r"((a)[3]), "r"((b)[0]), "r"((b)[1]))

struct EpiParams {
    const float* resid;
    const float* gate;
    const float* umat;
    __nv_bfloat16 *h0, *l0, *h1, *l1;
    float scale;
    int ldg;
    int rpb;
};

// ---------------- bf16x3 NT GEMM, 3-stage cp.async ring, 2 CTAs/SM ----------
// hi arrays: padded 80B rows (conflict-free); lo arrays: 64B rows (2-way ok).
#define SROWH 80
#define SROWL 64
#define OFF_AH 0
#define OFF_BH (128 * SROWH)                 // 10240
#define OFF_AL (2 * 128 * SROWH)             // 20480
#define OFF_BL (2 * 128 * SROWH + 128 * SROWL) // 28672
#define SLOT   (2 * 128 * SROWH + 2 * 128 * SROWL)  // 36864
#define MM_SMEM (3 * SLOT)                   // 110592

// Modes: 0 plain f32; 1 scale+mask f32; 2 PV scatter hi/lo; 4 +resid f32;
//        5 resid+acc*gate f32; 6 gelu(acc)*U -> hi/lo
template <int MODE>
__global__ void __launch_bounds__(256, 2) mgemm(
    const __nv_bfloat16* __restrict__ AgH, const __nv_bfloat16* __restrict__ AgL,
    const __nv_bfloat16* __restrict__ BgH, const __nv_bfloat16* __restrict__ BgL,
    float* __restrict__ Cg, int M, int N, int K,
    long long sAz, long long sBz, int bDivB, long long sCz, EpiParams ep)
{
    extern __shared__ char smem_raw[];
    uint32_t sbase = smem_u32(smem_raw);

    int tid = threadIdx.x;
    int wid = tid >> 5, lane = tid & 31;
    int g = lane >> 2, t4 = lane & 3;
    int wm = wid & 3, wn = wid >> 2;
    int z = blockIdx.z;
    const __nv_bfloat16* Ah = AgH + (size_t)z * (size_t)sAz;
    const __nv_bfloat16* Al = AgL + (size_t)z * (size_t)sAz;
    const __nv_bfloat16* Bh = BgH + (size_t)(z / bDivB) * (size_t)sBz;
    const __nv_bfloat16* Bl = BgL + (size_t)(z / bDivB) * (size_t)sBz;
    int m0 = blockIdx.y * 128;
    int n0 = blockIdx.x * 128;

    // ldmatrix lane offsets (hi: 80B stride, lo: 64B stride)
    uint32_t aoffH = (uint32_t)((wm * 32 + (lane & 15)) * SROWH + (lane >> 4) * 16);
    uint32_t boffH = (uint32_t)((wn * 64 + ((lane & 7) | ((lane >> 4) << 3))) * SROWH
                                + ((lane >> 3) & 1) * 16);
    uint32_t aoffL = (uint32_t)((wm * 32 + (lane & 15)) * SROWL + (lane >> 4) * 16);
    uint32_t boffL = (uint32_t)((wn * 64 + ((lane & 7) | ((lane >> 4) << 3))) * SROWL
                                + ((lane >> 3) & 1) * 16);

    float acc[2][8][4];
#pragma unroll
    for (int a = 0; a < 2; a++)
#pragma unroll
        for (int b = 0; b < 8; b++)
#pragma unroll
            for (int c = 0; c < 4; c++) acc[a][b][c] = 0.0f;

    int nc = (K + 31) / 32;

    auto issue = [&](int c) {
        uint32_t sb = sbase + (uint32_t)(c % 3) * SLOT;
        int k0 = c * 32;
#pragma unroll
        for (int it = 0; it < 2; ++it) {
            int ci = it * 256 + tid;                // 0..511
            int row = ci >> 2, cq = ci & 3;
            int kk = k0 + cq * 8;
            bool kv = kk < K;
            int gr = m0 + row;
            bool okA = kv && (gr < M);
            const __nv_bfloat16* sA = okA ? (Ah + (size_t)gr * K + kk) : Ah;
            const __nv_bfloat16* sAl = okA ? (Al + (size_t)gr * K + kk) : Al;
            CP_A16(sb + OFF_AH + (uint32_t)(row * SROWH + cq * 16), sA, okA ? 16 : 0);
            CP_A16(sb + OFF_AL + (uint32_t)(row * SROWL + cq * 16), sAl, okA ? 16 : 0);
            int gn = n0 + row;
            bool okB = kv && (gn < N);
            const __nv_bfloat16* sB = okB ? (Bh + (size_t)gn * K + kk) : Bh;
            const __nv_bfloat16* sBl = okB ? (Bl + (size_t)gn * K + kk) : Bl;
            CP_A16(sb + OFF_BH + (uint32_t)(row * SROWH + cq * 16), sB, okB ? 16 : 0);
            CP_A16(sb + OFF_BL + (uint32_t)(row * SROWL + cq * 16), sBl, okB ? 16 : 0);
        }
    };

    issue(0); CP_COMMIT();
    if (nc > 1) issue(1);
    CP_COMMIT();

    for (int c = 0; c < nc; ++c) {
        CP_WAIT1();                 // group c complete (c+1 may be in flight)
        __syncthreads();            // all CTA threads see slot c; slot (c+2)%3 free
        if (c + 2 < nc) issue(c + 2);
        CP_COMMIT();

        uint32_t sb = sbase + (uint32_t)(c % 3) * SLOT;
#pragma unroll
        for (int kk = 0; kk < 2; ++kk) {
            uint32_t kByte = (uint32_t)(kk * 32);
            uint32_t ah[2][4], al[2][4], bb[8][2];
            LDM_X4(ah[0], sb + OFF_AH + kByte + aoffH);
            LDM_X4(ah[1], sb + OFF_AH + kByte + aoffH + 16 * SROWH);
#pragma unroll
            for (int jp = 0; jp < 4; ++jp)
                LDM_X4(&bb[2 * jp][0], sb + OFF_BH + kByte + boffH + (uint32_t)(jp * 16 * SROWH));
#pragma unroll
            for (int mt = 0; mt < 2; ++mt)
#pragma unroll
                for (int j = 0; j < 8; ++j) MMA_BF16(acc[mt][j], ah[mt], bb[j]);
            LDM_X4(al[0], sb + OFF_AL + kByte + aoffL);
            LDM_X4(al[1], sb + OFF_AL + kByte + aoffL + 16 * SROWL);
#pragma unroll
            for (int mt = 0; mt < 2; ++mt)
#pragma unroll
                for (int j = 0; j < 8; ++j) MMA_BF16(acc[mt][j], al[mt], bb[j]);
#pragma unroll
            for (int jp = 0; jp < 4; ++jp)
                LDM_X4(&bb[2 * jp][0], sb + OFF_BL + kByte + boffL + (uint32_t)(jp * 16 * SROWL));
#pragma unroll
            for (int mt = 0; mt < 2; ++mt)
#pragma unroll
                for (int j = 0; j < 8; ++j) MMA_BF16(acc[mt][j], ah[mt], bb[j]);
        }
    }

    // ---------------- epilogue ----------------
#pragma unroll
    for (int mt = 0; mt < 2; ++mt) {
#pragma unroll
        for (int half = 0; half < 2; ++half) {
            int r = m0 + wm * 32 + mt * 16 + g + half * 8;
            if (r >= M) continue;
#pragma unroll
            for (int j = 0; j < 8; ++j) {
                int cc = n0 + wn * 64 + j * 8 + t4 * 2;
                if (cc >= N) continue;
                float v0 = acc[mt][j][half * 2 + 0];
                float v1 = acc[mt][j][half * 2 + 1];
                size_t idx = (size_t)r * N + cc;
                if constexpr (MODE == 0) {
                    *reinterpret_cast<float2*>(Cg + (size_t)z * sCz + idx) = make_float2(v0, v1);
                } else if constexpr (MODE == 1) {
                    float m0v = (r < SPq && cc >= SPq) ? MASKV : 0.0f;
                    float m1v = (r < SPq && cc + 1 >= SPq) ? MASKV : 0.0f;
                    *reinterpret_cast<float2*>(Cg + (size_t)z * sCz + idx) =
                        make_float2(v0 * ep.scale + m0v, v1 * ep.scale + m1v);
                } else if constexpr (MODE == 2) {
                    int b_ = z / bDivB, h_ = z % bDivB;
                    uint32_t hi, lo;
                    split2(v0, v1, hi, lo);
                    size_t off = (r < SPq)
                        ? ((size_t)b_ * SPq + r) * (Hq * HDq) + h_ * HDq + cc
                        : ((size_t)b_ * SSq + (r - SPq)) * (Hq * HDq) + h_ * HDq + cc;
                    __nv_bfloat16* dh = (r < SPq) ? ep.h0 : ep.h1;
                    __nv_bfloat16* dl = (r < SPq) ? ep.l0 : ep.l1;
                    *reinterpret_cast<uint32_t*>(dh + off) = hi;
                    *reinterpret_cast<uint32_t*>(dl + off) = lo;
                } else if constexpr (MODE == 4) {
                    float2 rs = *reinterpret_cast<const float2*>(ep.resid + idx);
                    *reinterpret_cast<float2*>(Cg + idx) = make_float2(rs.x + v0, rs.y + v1);
                } else if constexpr (MODE == 5) {
                    float2 rs = *reinterpret_cast<const float2*>(ep.resid + idx);
                    const float* gt = ep.gate + (size_t)(r / ep.rpb) * ep.ldg + cc;
                    *reinterpret_cast<float2*>(Cg + idx) =
                        make_float2(rs.x + v0 * gt[0], rs.y + v1 * gt[1]);
                } else if constexpr (MODE == 6) {
                    float2 um = *reinterpret_cast<const float2*>(ep.umat + idx);
                    float g0 = gelu_tanh(v0) * um.x;
                    float g1 = gelu_tanh(v1) * um.y;
                    uint32_t hi, lo;
                    split2(g0, g1, hi, lo);
                    *reinterpret_cast<uint32_t*>(ep.h0 + idx) = hi;
                    *reinterpret_cast<uint32_t*>(ep.l0 + idx) = lo;
                }
            }
        }
    }
}

// ---------------- weight split (f32 -> bf16 hi/lo) ----------------
__global__ void split_arr(const float* __restrict__ s, __nv_bfloat16* __restrict__ h,
                          __nv_bfloat16* __restrict__ l, size_t n)
{
    size_t i = ((size_t)blockIdx.x * 256 + threadIdx.x) * 4;
    if (i >= n) return;
    float4 v = *reinterpret_cast<const float4*>(s + i);
    uint32_t h0, l0, h1, l1;
    split2(v.x, v.y, h0, l0);
    split2(v.z, v.w, h1, l1);
    *reinterpret_cast<uint2*>(h + i) = make_uint2(h0, h1);
    *reinterpret_cast<uint2*>(l + i) = make_uint2(l0, l1);
}

// ---------------- small SIMT GEMM for cond modulation (M=8) -----------------
__global__ void __launch_bounds__(256) gemm_bias(
    const float* __restrict__ A, const float* __restrict__ B,
    const float* __restrict__ bias, float* __restrict__ C, int M, int N, int K)
{
    __shared__ float As[8][128];
    __shared__ float Bs[8][128];
    int m0 = blockIdx.y * 128, n0 = blockIdx.x * 128;
    int tid = threadIdx.x, tx = tid & 15, ty = tid >> 4;
    int ldRow = tid >> 1, ldCol = (tid & 1) * 4;
    float acc[8][8];
#pragma unroll
    for (int i = 0; i < 8; i++)
#pragma unroll
        for (int j = 0; j < 8; j++) acc[i][j] = 0.0f;
    for (int k0 = 0; k0 < K; k0 += 8) {
        float4 av = make_float4(0.f, 0.f, 0.f, 0.f);
        if (m0 + ldRow < M) av = *reinterpret_cast<const float4*>(A + (size_t)(m0 + ldRow) * K + k0 + ldCol);
        As[ldCol + 0][ldRow] = av.x; As[ldCol + 1][ldRow] = av.y;
        As[ldCol + 2][ldRow] = av.z; As[ldCol + 3][ldRow] = av.w;
        float4 bv = make_float4(0.f, 0.f, 0.f, 0.f);
        if (n0 + ldRow < N) bv = *reinterpret_cast<const float4*>(B + (size_t)(n0 + ldRow) * K + k0 + ldCol);
        Bs[ldCol + 0][ldRow] = bv.x; Bs[ldCol + 1][ldRow] = bv.y;
        Bs[ldCol + 2][ldRow] = bv.z; Bs[ldCol + 3][ldRow] = bv.w;
        __syncthreads();
#pragma unroll
        for (int kk = 0; kk < 8; kk++) {
            float a[8], b[8];
#pragma unroll
            for (int i = 0; i < 8; i++) a[i] = As[kk][ty * 8 + i];
#pragma unroll
            for (int j = 0; j < 8; j++) b[j] = Bs[kk][tx * 8 + j];
#pragma unroll
            for (int i = 0; i < 8; i++)
#pragma unroll
                for (int j = 0; j < 8; j++) acc[i][j] += a[i] * b[j];
        }
        __syncthreads();
    }
#pragma unroll
    for (int i = 0; i < 8; i++) {
        int r = m0 + ty * 8 + i;
        if (r >= M) continue;
#pragma unroll
        for (int j = 0; j < 8; j++) {
            int c = n0 + tx * 8 + j;
            if (c >= N) continue;
            C[(size_t)r * N + c] = acc[i][j] + bias[c];
        }
    }
}

// ---------------- norms (emit bf16 hi/lo) ----------------
__global__ void rmsnorm_split_k(const float* __restrict__ x, const float* __restrict__ w,
                                __nv_bfloat16* __restrict__ oh, __nv_bfloat16* __restrict__ ol, int D)
{
    int row = blockIdx.x;
    const float* xr = x + (size_t)row * D;
    float ss = 0.0f;
    for (int c = threadIdx.x; c < D; c += 256) { float v = xr[c]; ss += v * v; }
    __shared__ float red[256];
    red[threadIdx.x] = ss; __syncthreads();
    for (int s = 128; s > 0; s >>= 1) {
        if (threadIdx.x < s) red[threadIdx.x] += red[threadIdx.x + s];
        __syncthreads();
    }
    float rinv = rsqrtf(red[0] / (float)D + EPSq);
    size_t base = (size_t)row * D;
    for (int c = threadIdx.x * 2; c < D; c += 512) {
        float v0 = xr[c] * rinv * (1.0f + w[c]);
        float v1 = xr[c + 1] * rinv * (1.0f + w[c + 1]);
        uint32_t hi, lo;
        split2(v0, v1, hi, lo);
        *reinterpret_cast<uint32_t*>(oh + base + c) = hi;
        *reinterpret_cast<uint32_t*>(ol + base + c) = lo;
    }
}

__global__ void ada_norm_split_k(const float* __restrict__ x, const float* __restrict__ mod,
                                 __nv_bfloat16* __restrict__ oh, __nv_bfloat16* __restrict__ ol,
                                 int D, int rowsPerB)
{
    int row = blockIdx.x;
    int b = row / rowsPerB;
    const float* xr = x + (size_t)row * D;
    float ss = 0.0f;
    for (int c = threadIdx.x; c < D; c += 256) { float v = xr[c]; ss += v * v; }
    __shared__ float red[256];
    red[threadIdx.x] = ss; __syncthreads();
    for (int s = 128; s > 0; s >>= 1) {
        if (threadIdx.x < s) red[threadIdx.x] += red[threadIdx.x + s];
        __syncthreads();
    }
    float rinv = rsqrtf(red[0] / (float)D + EPSq);
    const float* mb = mod + (size_t)b * 3 * D;
    size_t base = (size_t)row * D;
    for (int c = threadIdx.x * 2; c < D; c += 512) {
        float v0 = xr[c] * rinv * (1.0f + mb[c]) + mb[D + c];
        float v1 = xr[c + 1] * rinv * (1.0f + mb[c + 1]) + mb[D + c + 1];
        uint32_t hi, lo;
        split2(v0, v1, hi, lo);
        *reinterpret_cast<uint32_t*>(oh + base + c) = hi;
        *reinterpret_cast<uint32_t*>(ol + base + c) = lo;
    }
}

// ---------------- rope / transpose from fused QKV (stride 2560) -------------
__global__ void rope_q_k(const float* __restrict__ qkvp, const float* __restrict__ qkvs,
                         __nv_bfloat16* __restrict__ qh, __nv_bfloat16* __restrict__ ql)
{
    size_t idx = (size_t)blockIdx.x * blockDim.x + threadIdx.x;
    const size_t total = (size_t)Bq * NTq * Hq * (HDq / 2);
    if (idx >= total) return;
    int d = (int)(idx % (HDq / 2)); size_t t = idx / (HDq / 2);
    int h = (int)(t % Hq); t /= Hq;
    int n = (int)(t % NTq); int b = (int)(t / NTq);
    const float* src = (n < SPq)
        ? qkvp + ((size_t)b * SPq + n) * NQKV + h * HDq
        : qkvs + ((size_t)b * SSq + (n - SPq)) * NQKV + h * HDq;
    float x1 = src[d], x2 = src[d + 128];
    float invf = powf(10000.0f, -(float)d * (1.0f / 128.0f));
    float ang = (float)n * invf;
    float cs = cosf(ang), sn = sinf(ang);
    size_t dst = (((size_t)b * Hq + h) * NTq + n) * HDq;
    emit1(qh, ql, dst + d, x1 * cs - x2 * sn);
    emit1(qh, ql, dst + d + 128, x2 * cs + x1 * sn);
}

__global__ void rope_k_k(const float* __restrict__ qkvp, const float* __restrict__ qkvs,
                         __nv_bfloat16* __restrict__ kh, __nv_bfloat16* __restrict__ kl)
{
    size_t idx = (size_t)blockIdx.x * blockDim.x + threadIdx.x;
    const size_t total = (size_t)Bq * NTq * (HDq / 2);
    if (idx >= total) return;
    int d = (int)(idx % (HDq / 2)); size_t t = idx / (HDq / 2);
    int n = (int)(t % NTq); int b = (int)(t / NTq);
    const float* src = (n < SPq)
        ? qkvp + ((size_t)b * SPq + n) * NQKV + (Hq * HDq)
        : qkvs + ((size_t)b * SSq + (n - SPq)) * NQKV + (Hq * HDq);
    float x1 = src[d], x2 = src[d + 128];
    float invf = powf(10000.0f, -(float)d * (1.0f / 128.0f));
    float ang = (float)n * invf;
    float cs = cosf(ang), sn = sinf(ang);
    size_t dst = ((size_t)b * NTq + n) * HDq;
    emit1(kh, kl, dst + d, x1 * cs - x2 * sn);
    emit1(kh, kl, dst + d + 128, x2 * cs + x1 * sn);
}

__global__ void transpose_v_k(const float* __restrict__ qkvp, const float* __restrict__ qkvs,
                              __nv_bfloat16* __restrict__ vh, __nv_bfloat16* __restrict__ vl)
{
    size_t idx = (size_t)blockIdx.x * blockDim.x + threadIdx.x;
    const size_t total = (size_t)Bq * NTq * HDq;
    if (idx >= total) return;
    int d = (int)(idx % HDq); size_t t = idx / HDq;
    int n = (int)(t % NTq); int b = (int)(t / NTq);
    float v = (n < SPq)
        ? qkvp[((size_t)b * SPq + n) * NQKV + (Hq * HDq + HDq) + d]
        : qkvs[((size_t)b * SSq + (n - SPq)) * NQKV + (Hq * HDq + HDq) + d];
    emit1(vh, vl, ((size_t)b * HDq + d) * NTq + n, v);
}

// ---------------- softmax (emit hi/lo) ----------------
__global__ void softmax_split_k(float* __restrict__ s, __nv_bfloat16* __restrict__ oh,
                                __nv_bfloat16* __restrict__ ol, int L)
{
    float* row = s + (size_t)blockIdx.x * L;
    __shared__ float red[256];
    float mx = -INFINITY;
    for (int c = threadIdx.x; c < L; c += 256) mx = fmaxf(mx, row[c]);
    red[threadIdx.x] = mx; __syncthreads();
    for (int st = 128; st > 0; st >>= 1) {
        if (threadIdx.x < st) red[threadIdx.x] = fmaxf(red[threadIdx.x], red[threadIdx.x + st]);
        __syncthreads();
    }
    mx = red[0]; __syncthreads();
    float sum = 0.0f;
    for (int c = threadIdx.x; c < L; c += 256) {
        float e = expf(row[c] - mx);
        row[c] = e; sum += e;
    }
    red[threadIdx.x] = sum; __syncthreads();
    for (int st = 128; st > 0; st >>= 1) {
        if (threadIdx.x < st) red[threadIdx.x] += red[threadIdx.x + st];
        __syncthreads();
    }
    float inv = 1.0f / red[0];
    size_t base = (size_t)blockIdx.x * L;
    for (int c = threadIdx.x * 2; c < L; c += 512) {
        float v0 = row[c] * inv;
        float v1 = row[c + 1] * inv;
        uint32_t hi, lo;
        split2(v0, v1, hi, lo);
        *reinterpret_cast<uint32_t*>(oh + base + c) = hi;
        *reinterpret_cast<uint32_t*>(ol + base + c) = lo;
    }
}

// ---------------- host-side dispatch ----------------
typedef __nv_bfloat16 bf16;

static void run_mm(int mode, const bf16* Ah, const bf16* Al, const bf16* Bh, const bf16* Bl,
                   float* C, int M, int N, int K,
                   long long sAz, long long sBz, int bDivB, long long sCz,
                   int Z, EpiParams ep)
{
    dim3 grid((N + 127) / 128, (M + 127) / 128, Z);
    switch (mode) {
        case 0:
            cudaFuncSetAttribute(mgemm<0>, cudaFuncAttributeMaxDynamicSharedMemorySize, MM_SMEM);
            mgemm<0><<<grid, 256, MM_SMEM>>>(Ah, Al, Bh, Bl, C, M, N, K, sAz, sBz, bDivB, sCz, ep); break;
        case 1:
            cudaFuncSetAttribute(mgemm<1>, cudaFuncAttributeMaxDynamicSharedMemorySize, MM_SMEM);
            mgemm<1><<<grid, 256, MM_SMEM>>>(Ah, Al, Bh, Bl, C, M, N, K, sAz, sBz, bDivB, sCz, ep); break;
        case 2:
            cudaFuncSetAttribute(mgemm<2>, cudaFuncAttributeMaxDynamicSharedMemorySize, MM_SMEM);
            mgemm<2><<<grid, 256, MM_SMEM>>>(Ah, Al, Bh, Bl, C, M, N, K, sAz, sBz, bDivB, sCz, ep); break;
        case 4:
            cudaFuncSetAttribute(mgemm<4>, cudaFuncAttributeMaxDynamicSharedMemorySize, MM_SMEM);
            mgemm<4><<<grid, 256, MM_SMEM>>>(Ah, Al, Bh, Bl, C, M, N, K, sAz, sBz, bDivB, sCz, ep); break;
        case 5:
            cudaFuncSetAttribute(mgemm<5>, cudaFuncAttributeMaxDynamicSharedMemorySize, MM_SMEM);
            mgemm<5><<<grid, 256, MM_SMEM>>>(Ah, Al, Bh, Bl, C, M, N, K, sAz, sBz, bDivB, sCz, ep); break;
        case 6:
            cudaFuncSetAttribute(mgemm<6>, cudaFuncAttributeMaxDynamicSharedMemorySize, MM_SMEM);
            mgemm<6><<<grid, 256, MM_SMEM>>>(Ah, Al, Bh, Bl, C, M, N, K, sAz, sBz, bDivB, sCz, ep); break;
    }
}

static void do_split(const float* s, bf16* h, bf16* l, size_t n)
{
    int blocks = (int)((n / 4 + 255) / 256);
    split_arr<<<blocks, 256>>>(s, h, l, n);
}

extern "C" void kernel_launch(void* const* d_in, const int* in_sizes, int n_in,
                              void* d_out, int out_size)
{
    const float* prefix_x    = (const float*)d_in[0];
    const float* suffix_x    = (const float*)d_in[1];
    const float* cond        = (const float*)d_in[2];
    const float* p_ln_w      = (const float*)d_in[3];
    const float* p_q_w       = (const float*)d_in[4];
    const float* p_k_w       = (const float*)d_in[5];
    const float* p_v_w       = (const float*)d_in[6];
    const float* p_o_w       = (const float*)d_in[7];
    const float* p_post_ln_w = (const float*)d_in[8];
    const float* p_gate_w    = (const float*)d_in[9];
    const float* p_up_w      = (const float*)d_in[10];
    const float* p_down_w    = (const float*)d_in[11];
    const float* s_ada1_w    = (const float*)d_in[12];
    const float* s_ada1_b    = (const float*)d_in[13];
    const float* s_q_w       = (const float*)d_in[14];
    const float* s_k_w       = (const float*)d_in[15];
    const float* s_v_w       = (const float*)d_in[16];
    const float* s_o_w       = (const float*)d_in[17];
    const float* s_ada2_w    = (const float*)d_in[18];
    const float* s_ada2_b    = (const float*)d_in[19];
    const float* s_gate_w    = (const float*)d_in[20];
    const float* s_up_w      = (const float*)d_in[21];
    const float* s_down_w    = (const float*)d_in[22];

    float* scr = nullptr;
    cudaGetSymbolAddress((void**)&scr, g_scr);
    bf16* sh = nullptr;
    cudaGetSymbolAddress((void**)&sh, g_scrh);
    bf16* sl = sh + SET_TOTAL;

    float* mod1  = scr + O_MOD1;
    float* mod2  = scr + O_MOD2;
    float* qkvp  = scr + O_QKVP;
    float* qkvs  = scr + O_QKVS;
    float* sc    = scr + O_SCF;
    float* Up    = scr + O_UPF;
    float* Us    = scr + O_USF;
    float* res_p = scr + O_RESP;
    float* res_s = scr + O_RESS;

    float* outp = (float*)d_out;
    float* outs = outp + NPROW * DPq;

    EpiParams ep0 = {};

    // 0) weight splits (QKV blocks land contiguously -> fused weight matrices)
    do_split(p_q_w,    sh + B_WPQ, sl + B_WPQ, (size_t)(Hq*HDq)*DPq);
    do_split(p_k_w,    sh + B_WPK, sl + B_WPK, (size_t)HDq*DPq);
    do_split(p_v_w,    sh + B_WPV, sl + B_WPV, (size_t)HDq*DPq);
    do_split(p_o_w,    sh + B_WPO, sl + B_WPO, (size_t)DPq*(Hq*HDq));
    do_split(p_gate_w, sh + B_WPG, sl + B_WPG, (size_t)FPq*DPq);
    do_split(p_up_w,   sh + B_WPU, sl + B_WPU, (size_t)FPq*DPq);
    do_split(p_down_w, sh + B_WPD, sl + B_WPD, (size_t)DPq*FPq);
    do_split(s_q_w,    sh + B_WSQ, sl + B_WSQ, (size_t)(Hq*HDq)*DSq);
    do_split(s_k_w,    sh + B_WSK, sl + B_WSK, (size_t)HDq*DSq);
    do_split(s_v_w,    sh + B_WSV, sl + B_WSV, (size_t)HDq*DSq);
    do_split(s_o_w,    sh + B_WSO, sl + B_WSO, (size_t)DSq*(Hq*HDq));
    do_split(s_gate_w, sh + B_WSG, sl + B_WSG, (size_t)FSq*DSq);
    do_split(s_up_w,   sh + B_WSU, sl + B_WSU, (size_t)FSq*DSq);
    do_split(s_down_w, sh + B_WSD, sl + B_WSD, (size_t)DSq*FSq);

    // 1) norms + ada modulation
    rmsnorm_split_k<<<(int)NPROW, 256>>>(prefix_x, p_ln_w, sh + B_HP, sl + B_HP, DPq);
    gemm_bias<<<dim3(24, 1, 1), 256>>>(cond, s_ada1_w, s_ada1_b, mod1, Bq, 3 * DSq, DCq);
    ada_norm_split_k<<<(int)NSROW, 256>>>(suffix_x, mod1, sh + B_HS, sl + B_HS, DSq, SSq);

    // 2) fused QKV projections (one GEMM per stream, N=2560)
    run_mm(0, sh + B_HP, sl + B_HP, sh + B_WPQ, sl + B_WPQ, qkvp, (int)NPROW, NQKV, DPq, 0, 0, 1, 0, 1, ep0);
    run_mm(0, sh + B_HS, sl + B_HS, sh + B_WSQ, sl + B_WSQ, qkvs, (int)NSROW, NQKV, DSq, 0, 0, 1, 0, 1, ep0);

    // 3) RoPE + layouts (emit hi/lo)
    {
        size_t tq = (size_t)Bq * NTq * Hq * (HDq / 2);
        rope_q_k<<<(int)((tq + 255) / 256), 256>>>(qkvp, qkvs, sh + B_Q, sl + B_Q);
        size_t tk = (size_t)Bq * NTq * (HDq / 2);
        rope_k_k<<<(int)((tk + 255) / 256), 256>>>(qkvp, qkvs, sh + B_K, sl + B_K);
        size_t tv = (size_t)Bq * NTq * HDq;
        transpose_v_k<<<(int)((tv + 255) / 256), 256>>>(qkvp, qkvs, sh + B_VT, sl + B_VT);
    }

    // 4) attention
    { EpiParams e = ep0; e.scale = 0.0625f;
      run_mm(1, sh + B_Q, sl + B_Q, sh + B_K, sl + B_K, sc, NTq, NTq, HDq,
             (long long)NTq * HDq, (long long)NTq * HDq, Hq,
             (long long)NTq * NTq, Bq * Hq, e); }
    softmax_split_k<<<Bq * Hq * NTq, 256>>>(sc, sh + B_SC, sl + B_SC, NTq);
    { EpiParams e = ep0; e.h0 = sh + B_AP; e.l0 = sl + B_AP; e.h1 = sh + B_AS; e.l1 = sl + B_AS;
      run_mm(2, sh + B_SC, sl + B_SC, sh + B_VT, sl + B_VT, nullptr, NTq, HDq, NTq,
             (long long)NTq * NTq, (long long)HDq * NTq, Hq, 0, Bq * Hq, e); }

    // 5) prefix: o-proj + residual, post-norm, MLP
    { EpiParams e = ep0; e.resid = prefix_x;
      run_mm(4, sh + B_AP, sl + B_AP, sh + B_WPO, sl + B_WPO, res_p, (int)NPROW, DPq, Hq * HDq, 0, 0, 1, 0, 1, e); }
    rmsnorm_split_k<<<(int)NPROW, 256>>>(res_p, p_post_ln_w, sh + B_HP2, sl + B_HP2, DPq);
    run_mm(0, sh + B_HP2, sl + B_HP2, sh + B_WPU, sl + B_WPU, Up, (int)NPROW, FPq, DPq, 0, 0, 1, 0, 1, ep0);
    { EpiParams e = ep0; e.umat = Up; e.h0 = sh + B_HPM; e.l0 = sl + B_HPM;
      run_mm(6, sh + B_HP2, sl + B_HP2, sh + B_WPG, sl + B_WPG, nullptr, (int)NPROW, FPq, DPq, 0, 0, 1, 0, 1, e); }
    { EpiParams e = ep0; e.resid = res_p;
      run_mm(4, sh + B_HPM, sl + B_HPM, sh + B_WPD, sl + B_WPD, outp, (int)NPROW, DPq, FPq, 0, 0, 1, 0, 1, e); }

    // 6) suffix: gated o-proj + residual, ada-norm2, gated MLP
    { EpiParams e = ep0; e.resid = suffix_x; e.gate = mod1 + 2 * DSq; e.ldg = 3 * DSq; e.rpb = SSq;
      run_mm(5, sh + B_AS, sl + B_AS, sh + B_WSO, sl + B_WSO, res_s, (int)NSROW, DSq, Hq * HDq, 0, 0, 1, 0, 1, e); }
    gemm_bias<<<dim3(24, 1, 1), 256>>>(cond, s_ada2_w, s_ada2_b, mod2, Bq, 3 * DSq, DCq);
    ada_norm_split_k<<<(int)NSROW, 256>>>(res_s, mod2, sh + B_H2S, sl + B_H2S, DSq, SSq);
    run_mm(0, sh + B_H2S, sl + B_H2S, sh + B_WSU, sl + B_WSU, Us, (int)NSROW, FSq, DSq, 0, 0, 1, 0, 1, ep0);
    { EpiParams e = ep0; e.umat = Us; e.h0 = sh + B_HSM; e.l0 = sl + B_HSM;
      run_mm(6, sh + B_H2S, sl + B_H2S, sh + B_WSG, sl + B_WSG, nullptr, (int)NSROW, FSq, DSq, 0, 0, 1, 0, 1, e); }
    { EpiParams e = ep0; e.resid = res_s; e.gate = mod2 + 2 * DSq; e.ldg = 3 * DSq; e.rpb = SSq;
      run_mm(5, sh + B_HSM, sl + B_HSM, sh + B_WSD, sl + B_WSD, outs, (int)NSROW, DSq, FSq, 0, 0, 1, 0, 1, e); }
}

// round 14
// speedup vs baseline: 1.0709x; 1.0709x over previous
#include <cuda_runtime.h>
#include <cuda_bf16.h>
#include <math.h>
#include <stdint.h>

// ---------------- problem constants ----------------
#define Bq   8
#define SPq  800
#define SSq  48
#define NTq  848
#define DPq  2048
#define DSq  1024
#define DCq  1024
#define Hq   8
#define HDq  256
#define FPq  16384
#define FSq  4096
#define EPSq 1e-6f
#define MASKV (-2.3819763e+38f)
#define NQKV 2560                 // fused QKV output cols

static constexpr size_t NPROW = (size_t)Bq * SPq;   // 6400
static constexpr size_t NSROW = (size_t)Bq * SSq;   // 384

// ---------------- f32 scratch ----------------
static constexpr size_t O_MOD1 = 0;
static constexpr size_t O_MOD2 = O_MOD1 + (size_t)Bq * 3 * DSq;
static constexpr size_t O_QKVP = O_MOD2 + (size_t)Bq * 3 * DSq;           // [6400,2560]
static constexpr size_t O_QKVS = O_QKVP + NPROW * (size_t)NQKV;           // [384,2560]
static constexpr size_t O_SCF  = O_QKVS + NSROW * (size_t)NQKV;           // scores f32
static constexpr size_t O_RESP = O_SCF  + (size_t)Bq*Hq*NTq*NTq;
static constexpr size_t O_RESS = O_RESP + NPROW * DPq;
static constexpr size_t F32_TOTAL = O_RESS + NSROW * DSq;

__device__ float g_scr[F32_TOTAL];

// ---------------- bf16 scratch (hi set + lo set) ----------------
static constexpr size_t B_HP   = 0;
static constexpr size_t B_HS   = B_HP  + NPROW * DPq;
static constexpr size_t B_Q    = B_HS  + NSROW * DSq;
static constexpr size_t B_K    = B_Q   + (size_t)Bq*Hq*NTq*HDq;
static constexpr size_t B_VT   = B_K   + (size_t)Bq*NTq*HDq;
static constexpr size_t B_SC   = B_VT  + (size_t)Bq*NTq*HDq;
static constexpr size_t B_AP   = B_SC  + (size_t)Bq*Hq*NTq*NTq;
static constexpr size_t B_AS   = B_AP  + NPROW * (size_t)(Hq*HDq);
static constexpr size_t B_HP2  = B_AS  + NSROW * (size_t)(Hq*HDq);
static constexpr size_t B_HPM  = B_HP2 + NPROW * DPq;
static constexpr size_t B_H2S  = B_HPM + NPROW * FPq;
static constexpr size_t B_HSM  = B_H2S + NSROW * DSq;
static constexpr size_t B_WPQ  = B_HSM + NSROW * FSq;                     // Wq|Wk|Wv contiguous
static constexpr size_t B_WPK  = B_WPQ + (size_t)(Hq*HDq)*DPq;
static constexpr size_t B_WPV  = B_WPK + (size_t)HDq*DPq;
static constexpr size_t B_WPO  = B_WPV + (size_t)HDq*DPq;
static constexpr size_t B_WGU  = B_WPO + (size_t)DPq*(Hq*HDq);            // interleaved gate/up [2*FP, DP]
static constexpr size_t B_WPD  = B_WGU + 2*(size_t)FPq*DPq;
static constexpr size_t B_WSQ  = B_WPD + (size_t)DPq*FPq;                 // Wq|Wk|Wv contiguous
static constexpr size_t B_WSK  = B_WSQ + (size_t)(Hq*HDq)*DSq;
static constexpr size_t B_WSV  = B_WSK + (size_t)HDq*DSq;
static constexpr size_t B_WSO  = B_WSV + (size_t)HDq*DSq;
static constexpr size_t B_WSGU = B_WSO + (size_t)DSq*(Hq*HDq);            // interleaved [2*FS, DS]
static constexpr size_t B_WSD  = B_WSGU + 2*(size_t)FSq*DSq;
static constexpr size_t SET_TOTAL = B_WSD + (size_t)DSq*FSq;

__device__ __nv_bfloat16 g_scrh[2 * SET_TOTAL];

// ---------------- helpers ----------------
__device__ __forceinline__ uint32_t smem_u32(const void* p) {
    uint32_t a;
    asm("{ .reg .u64 t; cvta.to.shared.u64 t, %1; cvt.u32.u64 %0, t; }" : "=r"(a) : "l"(p));
    return a;
}
#define LDM_X4(R, addr) \
    asm volatile("ldmatrix.sync.aligned.m8n8.x4.shared.b16 {%0,%1,%2,%3}, [%4];" \
        : "=r"((R)[0]), "=r"((R)[1]), "=r"((R)[2]), "=r"((R)[3]) : "r"(addr))
#define CP_A16(dst, src, sz) \
    asm volatile("cp.async.cg.shared.global [%0], [%1], 16, %2;" \
        :: "r"(dst), "l"(src), "r"(sz) : "memory")
#define CP_COMMIT() asm volatile("cp.async.commit_group;" ::: "memory")
#define CP_WAIT1()  asm volatile("cp.async.wait_group 1;" ::: "memory")

__device__ __forceinline__ float gelu_tanh(float x) {
    float x3 = x * x * x;
    return 0.5f * x * (1.0f + tanhf(0.7978845608028654f * (x + 0.044715f * x3)));
}
__device__ __forceinline__ void split2(float x, float y, uint32_t& hi, uint32_t& lo) {
    __nv_bfloat16 hx = __float2bfloat16_rn(x);
    __nv_bfloat16 hy = __float2bfloat16_rn(y);
    float rx = x - __bfloat162float(hx);
    float ry = y - __bfloat162float(hy);
    __nv_bfloat16 lx = __float2bfloat16_rn(rx);
    __nv_bfloat16 ly = __float2bfloat16_rn(ry);
    hi = (uint32_t)__bfloat16_as_ushort(hx) | ((uint32_t)__bfloat16_as_ushort(hy) << 16);
    lo = (uint32_t)__bfloat16_as_ushort(lx) | ((uint32_t)__bfloat16_as_ushort(ly) << 16);
}
__device__ __forceinline__ void emit1(__nv_bfloat16* h, __nv_bfloat16* l, size_t off, float v) {
    __nv_bfloat16 hv = __float2bfloat16_rn(v);
    h[off] = hv;
    l[off] = __float2bfloat16_rn(v - __bfloat162float(hv));
}

#define MMA_BF16(d, a, b) \
    asm volatile("mma.sync.aligned.m16n8k16.row.col.f32.bf16.bf16.f32 " \
        "{%0,%1,%2,%3}, {%4,%5,%6,%7}, {%8,%9}, {%0,%1,%2,%3};" \
        : "+f"((d)[0]), "+f"((d)[1]), "+f"((d)[2]), "+f"((d)[3]) \
        : "r"((a)[0]), "r"((a)[1]), "r"((a)[2]), "r"((a)[3]), "r"((b)[0]), "r"((b)[1]))

struct EpiParams {
    const float* resid;
    const float* gate;
    __nv_bfloat16 *h0, *l0, *h1, *l1;
    float scale;
    int ldg;
    int rpb;
};

// ---------------- bf16x3 NT GEMM, 2-stage cp.async ring, 2 CTAs/SM ----------
// (R12-proven mainloop: all tiles padded 80B rows, conflict-free ldmatrix.)
#define SROW 80
#define SUB  (128 * SROW)            // 10240
#define OFF_AH 0
#define OFF_AL (1 * SUB)
#define OFF_BH (2 * SUB)
#define OFF_BL (3 * SUB)
#define SLOT   (4 * SUB)             // 40960
#define MM_SMEM (2 * SLOT)           // 81920 -> 2 CTAs/SM

// Modes: 0 plain f32; 1 scale+mask f32; 2 PV scatter hi/lo; 4 +resid f32;
//        5 resid+acc*gate f32; 7 interleaved gelu(gate)*up -> hi/lo (out N/2)
template <int MODE>
__global__ void __launch_bounds__(256, 2) mgemm(
    const __nv_bfloat16* __restrict__ AgH, const __nv_bfloat16* __restrict__ AgL,
    const __nv_bfloat16* __restrict__ BgH, const __nv_bfloat16* __restrict__ BgL,
    float* __restrict__ Cg, int M, int N, int K,
    long long sAz, long long sBz, int bDivB, long long sCz, EpiParams ep)
{
    extern __shared__ char smem_raw[];
    uint32_t sbase = smem_u32(smem_raw);

    int tid = threadIdx.x;
    int wid = tid >> 5, lane = tid & 31;
    int g = lane >> 2, t4 = lane & 3;
    int wm = wid & 3, wn = wid >> 2;
    int z = blockIdx.z;
    const __nv_bfloat16* Ah = AgH + (size_t)z * (size_t)sAz;
    const __nv_bfloat16* Al = AgL + (size_t)z * (size_t)sAz;
    const __nv_bfloat16* Bh = BgH + (size_t)(z / bDivB) * (size_t)sBz;
    const __nv_bfloat16* Bl = BgL + (size_t)(z / bDivB) * (size_t)sBz;
    int m0 = blockIdx.y * 128;
    int n0 = blockIdx.x * 128;

    uint32_t aoff = (uint32_t)((wm * 32 + (lane & 15)) * SROW + (lane >> 4) * 16);
    uint32_t boff = (uint32_t)((wn * 64 + ((lane & 7) | ((lane >> 4) << 3))) * SROW
                               + ((lane >> 3) & 1) * 16);

    float acc[2][8][4];
#pragma unroll
    for (int a = 0; a < 2; a++)
#pragma unroll
        for (int b = 0; b < 8; b++)
#pragma unroll
            for (int c = 0; c < 4; c++) acc[a][b][c] = 0.0f;

    int nc = (K + 31) / 32;

    auto issue = [&](int c) {
        uint32_t sb = sbase + (c & 1) * SLOT;
        int k0 = c * 32;
#pragma unroll
        for (int it = 0; it < 2; ++it) {
            int ci = it * 256 + tid;
            int row = ci >> 2, cq = ci & 3;
            int kk = k0 + cq * 8;
            bool kv = kk < K;
            uint32_t dst = sb + (uint32_t)(row * SROW + cq * 16);
            int gr = m0 + row;
            bool okA = kv && (gr < M);
            const __nv_bfloat16* sA = okA ? (Ah + (size_t)gr * K + kk) : Ah;
            const __nv_bfloat16* sAl = okA ? (Al + (size_t)gr * K + kk) : Al;
            CP_A16(dst + OFF_AH, sA, okA ? 16 : 0);
            CP_A16(dst + OFF_AL, sAl, okA ? 16 : 0);
            int gn = n0 + row;
            bool okB = kv && (gn < N);
            const __nv_bfloat16* sB = okB ? (Bh + (size_t)gn * K + kk) : Bh;
            const __nv_bfloat16* sBl = okB ? (Bl + (size_t)gn * K + kk) : Bl;
            CP_A16(dst + OFF_BH, sB, okB ? 16 : 0);
            CP_A16(dst + OFF_BL, sBl, okB ? 16 : 0);
        }
    };

    issue(0); CP_COMMIT();
    if (nc > 1) issue(1);
    CP_COMMIT();

    for (int c = 0; c < nc; ++c) {
        CP_WAIT1();
        __syncthreads();
        uint32_t sb = sbase + (c & 1) * SLOT;
#pragma unroll
        for (int kk = 0; kk < 2; ++kk) {
            uint32_t kByte = (uint32_t)(kk * 32);
            uint32_t ah[2][4], al[2][4], bb[8][2];
            LDM_X4(ah[0], sb + OFF_AH + kByte + aoff);
            LDM_X4(ah[1], sb + OFF_AH + kByte + aoff + 16 * SROW);
#pragma unroll
            for (int jp = 0; jp < 4; ++jp)
                LDM_X4(&bb[2 * jp][0], sb + OFF_BH + kByte + boff + (uint32_t)(jp * 16 * SROW));
#pragma unroll
            for (int mt = 0; mt < 2; ++mt)
#pragma unroll
                for (int j = 0; j < 8; ++j) MMA_BF16(acc[mt][j], ah[mt], bb[j]);
            LDM_X4(al[0], sb + OFF_AL + kByte + aoff);
            LDM_X4(al[1], sb + OFF_AL + kByte + aoff + 16 * SROW);
#pragma unroll
            for (int mt = 0; mt < 2; ++mt)
#pragma unroll
                for (int j = 0; j < 8; ++j) MMA_BF16(acc[mt][j], al[mt], bb[j]);
#pragma unroll
            for (int jp = 0; jp < 4; ++jp)
                LDM_X4(&bb[2 * jp][0], sb + OFF_BL + kByte + boff + (uint32_t)(jp * 16 * SROW));
#pragma unroll
            for (int mt = 0; mt < 2; ++mt)
#pragma unroll
                for (int j = 0; j < 8; ++j) MMA_BF16(acc[mt][j], ah[mt], bb[j]);
        }
        __syncthreads();
        if (c + 2 < nc) issue(c + 2);
        CP_COMMIT();
    }

    // ---------------- epilogue ----------------
#pragma unroll
    for (int mt = 0; mt < 2; ++mt) {
#pragma unroll
        for (int half = 0; half < 2; ++half) {
            int r = m0 + wm * 32 + mt * 16 + g + half * 8;
            if (r >= M) continue;
#pragma unroll
            for (int j = 0; j < 8; ++j) {
                int cc = n0 + wn * 64 + j * 8 + t4 * 2;
                if (cc >= N) continue;
                float v0 = acc[mt][j][half * 2 + 0];
                float v1 = acc[mt][j][half * 2 + 1];
                size_t idx = (size_t)r * N + cc;
                if constexpr (MODE == 0) {
                    *reinterpret_cast<float2*>(Cg + (size_t)z * sCz + idx) = make_float2(v0, v1);
                } else if constexpr (MODE == 1) {
                    float m0v = (r < SPq && cc >= SPq) ? MASKV : 0.0f;
                    float m1v = (r < SPq && cc + 1 >= SPq) ? MASKV : 0.0f;
                    *reinterpret_cast<float2*>(Cg + (size_t)z * sCz + idx) =
                        make_float2(v0 * ep.scale + m0v, v1 * ep.scale + m1v);
                } else if constexpr (MODE == 2) {
                    int b_ = z / bDivB, h_ = z % bDivB;
                    uint32_t hi, lo;
                    split2(v0, v1, hi, lo);
                    size_t off = (r < SPq)
                        ? ((size_t)b_ * SPq + r) * (Hq * HDq) + h_ * HDq + cc
                        : ((size_t)b_ * SSq + (r - SPq)) * (Hq * HDq) + h_ * HDq + cc;
                    __nv_bfloat16* dh = (r < SPq) ? ep.h0 : ep.h1;
                    __nv_bfloat16* dl = (r < SPq) ? ep.l0 : ep.l1;
                    *reinterpret_cast<uint32_t*>(dh + off) = hi;
                    *reinterpret_cast<uint32_t*>(dl + off) = lo;
                } else if constexpr (MODE == 4) {
                    float2 rs = *reinterpret_cast<const float2*>(ep.resid + idx);
                    *reinterpret_cast<float2*>(Cg + idx) = make_float2(rs.x + v0, rs.y + v1);
                } else if constexpr (MODE == 5) {
                    float2 rs = *reinterpret_cast<const float2*>(ep.resid + idx);
                    const float* gt = ep.gate + (size_t)(r / ep.rpb) * ep.ldg + cc;
                    *reinterpret_cast<float2*>(Cg + idx) =
                        make_float2(rs.x + v0 * gt[0], rs.y + v1 * gt[1]);
                } else if constexpr (MODE == 7) {
                    // interleaved: even col = gate, odd col = up; out col = cc/2
                    float gv = gelu_tanh(v0) * v1;
                    emit1(ep.h0, ep.l0, (size_t)r * (size_t)(N >> 1) + (size_t)(cc >> 1), gv);
                }
            }
        }
    }
}

// ---------------- weight split (f32 -> bf16 hi/lo) ----------------
__global__ void split_arr(const float* __restrict__ s, __nv_bfloat16* __restrict__ h,
                          __nv_bfloat16* __restrict__ l, size_t n)
{
    size_t i = ((size_t)blockIdx.x * 256 + threadIdx.x) * 4;
    if (i >= n) return;
    float4 v = *reinterpret_cast<const float4*>(s + i);
    uint32_t h0, l0, h1, l1;
    split2(v.x, v.y, h0, l0);
    split2(v.z, v.w, h1, l1);
    *reinterpret_cast<uint2*>(h + i) = make_uint2(h0, h1);
    *reinterpret_cast<uint2*>(l + i) = make_uint2(l0, l1);
}

// interleaved split: src row r -> dst row 2r+which (row-major [rows,K])
__global__ void split_ilv(const float* __restrict__ s, __nv_bfloat16* __restrict__ h,
                          __nv_bfloat16* __restrict__ l, size_t n, int K, int which)
{
    size_t i = ((size_t)blockIdx.x * 256 + threadIdx.x) * 4;
    if (i >= n) return;
    size_t r = i / (size_t)K;
    int k = (int)(i - r * (size_t)K);
    size_t o = ((r << 1) | (size_t)which) * (size_t)K + (size_t)k;
    float4 v = *reinterpret_cast<const float4*>(s + i);
    uint32_t h0, l0, h1, l1;
    split2(v.x, v.y, h0, l0);
    split2(v.z, v.w, h1, l1);
    *reinterpret_cast<uint2*>(h + o) = make_uint2(h0, h1);
    *reinterpret_cast<uint2*>(l + o) = make_uint2(l0, l1);
}

// ---------------- small SIMT GEMM for cond modulation (M=8) -----------------
__global__ void __launch_bounds__(256) gemm_bias(
    const float* __restrict__ A, const float* __restrict__ B,
    const float* __restrict__ bias, float* __restrict__ C, int M, int N, int K)
{
    __shared__ float As[8][128];
    __shared__ float Bs[8][128];
    int m0 = blockIdx.y * 128, n0 = blockIdx.x * 128;
    int tid = threadIdx.x, tx = tid & 15, ty = tid >> 4;
    int ldRow = tid >> 1, ldCol = (tid & 1) * 4;
    float acc[8][8];
#pragma unroll
    for (int i = 0; i < 8; i++)
#pragma unroll
        for (int j = 0; j < 8; j++) acc[i][j] = 0.0f;
    for (int k0 = 0; k0 < K; k0 += 8) {
        float4 av = make_float4(0.f, 0.f, 0.f, 0.f);
        if (m0 + ldRow < M) av = *reinterpret_cast<const float4*>(A + (size_t)(m0 + ldRow) * K + k0 + ldCol);
        As[ldCol + 0][ldRow] = av.x; As[ldCol + 1][ldRow] = av.y;
        As[ldCol + 2][ldRow] = av.z; As[ldCol + 3][ldRow] = av.w;
        float4 bv = make_float4(0.f, 0.f, 0.f, 0.f);
        if (n0 + ldRow < N) bv = *reinterpret_cast<const float4*>(B + (size_t)(n0 + ldRow) * K + k0 + ldCol);
        Bs[ldCol + 0][ldRow] = bv.x; Bs[ldCol + 1][ldRow] = bv.y;
        Bs[ldCol + 2][ldRow] = bv.z; Bs[ldCol + 3][ldRow] = bv.w;
        __syncthreads();
#pragma unroll
        for (int kk = 0; kk < 8; kk++) {
            float a[8], b[8];
#pragma unroll
            for (int i = 0; i < 8; i++) a[i] = As[kk][ty * 8 + i];
#pragma unroll
            for (int j = 0; j < 8; j++) b[j] = Bs[kk][tx * 8 + j];
#pragma unroll
            for (int i = 0; i < 8; i++)
#pragma unroll
                for (int j = 0; j < 8; j++) acc[i][j] += a[i] * b[j];
        }
        __syncthreads();
    }
#pragma unroll
    for (int i = 0; i < 8; i++) {
        int r = m0 + ty * 8 + i;
        if (r >= M) continue;
#pragma unroll
        for (int j = 0; j < 8; j++) {
            int c = n0 + tx * 8 + j;
            if (c >= N) continue;
            C[(size_t)r * N + c] = acc[i][j] + bias[c];
        }
    }
}

// ---------------- norms (emit bf16 hi/lo) ----------------
__global__ void rmsnorm_split_k(const float* __restrict__ x, const float* __restrict__ w,
                                __nv_bfloat16* __restrict__ oh, __nv_bfloat16* __restrict__ ol, int D)
{
    int row = blockIdx.x;
    const float* xr = x + (size_t)row * D;
    float ss = 0.0f;
    for (int c = threadIdx.x; c < D; c += 256) { float v = xr[c]; ss += v * v; }
    __shared__ float red[256];
    red[threadIdx.x] = ss; __syncthreads();
    for (int s = 128; s > 0; s >>= 1) {
        if (threadIdx.x < s) red[threadIdx.x] += red[threadIdx.x + s];
        __syncthreads();
    }
    float rinv = rsqrtf(red[0] / (float)D + EPSq);
    size_t base = (size_t)row * D;
    for (int c = threadIdx.x * 2; c < D; c += 512) {
        float v0 = xr[c] * rinv * (1.0f + w[c]);
        float v1 = xr[c + 1] * rinv * (1.0f + w[c + 1]);
        uint32_t hi, lo;
        split2(v0, v1, hi, lo);
        *reinterpret_cast<uint32_t*>(oh + base + c) = hi;
        *reinterpret_cast<uint32_t*>(ol + base + c) = lo;
    }
}

__global__ void ada_norm_split_k(const float* __restrict__ x, const float* __restrict__ mod,
                                 __nv_bfloat16* __restrict__ oh, __nv_bfloat16* __restrict__ ol,
                                 int D, int rowsPerB)
{
    int row = blockIdx.x;
    int b = row / rowsPerB;
    const float* xr = x + (size_t)row * D;
    float ss = 0.0f;
    for (int c = threadIdx.x; c < D; c += 256) { float v = xr[c]; ss += v * v; }
    __shared__ float red[256];
    red[threadIdx.x] = ss; __syncthreads();
    for (int s = 128; s > 0; s >>= 1) {
        if (threadIdx.x < s) red[threadIdx.x] += red[threadIdx.x + s];
        __syncthreads();
    }
    float rinv = rsqrtf(red[0] / (float)D + EPSq);
    const float* mb = mod + (size_t)b * 3 * D;
    size_t base = (size_t)row * D;
    for (int c = threadIdx.x * 2; c < D; c += 512) {
        float v0 = xr[c] * rinv * (1.0f + mb[c]) + mb[D + c];
        float v1 = xr[c + 1] * rinv * (1.0f + mb[c + 1]) + mb[D + c + 1];
        uint32_t hi, lo;
        split2(v0, v1, hi, lo);
        *reinterpret_cast<uint32_t*>(oh + base + c) = hi;
        *reinterpret_cast<uint32_t*>(ol + base + c) = lo;
    }
}

// ---------------- rope / transpose from fused QKV (stride 2560) -------------
__global__ void rope_q_k(const float* __restrict__ qkvp, const float* __restrict__ qkvs,
                         __nv_bfloat16* __restrict__ qh, __nv_bfloat16* __restrict__ ql)
{
    size_t idx = (size_t)blockIdx.x * blockDim.x + threadIdx.x;
    const size_t total = (size_t)Bq * NTq * Hq * (HDq / 2);
    if (idx >= total) return;
    int d = (int)(idx % (HDq / 2)); size_t t = idx / (HDq / 2);
    int h = (int)(t % Hq); t /= Hq;
    int n = (int)(t % NTq); int b = (int)(t / NTq);
    const float* src = (n < SPq)
        ? qkvp + ((size_t)b * SPq + n) * NQKV + h * HDq
        : qkvs + ((size_t)b * SSq + (n - SPq)) * NQKV + h * HDq;
    float x1 = src[d], x2 = src[d + 128];
    float invf = powf(10000.0f, -(float)d * (1.0f / 128.0f));
    float ang = (float)n * invf;
    float cs = cosf(ang), sn = sinf(ang);
    size_t dst = (((size_t)b * Hq + h) * NTq + n) * HDq;
    emit1(qh, ql, dst + d, x1 * cs - x2 * sn);
    emit1(qh, ql, dst + d + 128, x2 * cs + x1 * sn);
}

__global__ void rope_k_k(const float* __restrict__ qkvp, const float* __restrict__ qkvs,
                         __nv_bfloat16* __restrict__ kh, __nv_bfloat16* __restrict__ kl)
{
    size_t idx = (size_t)blockIdx.x * blockDim.x + threadIdx.x;
    const size_t total = (size_t)Bq * NTq * (HDq / 2);
    if (idx >= total) return;
    int d = (int)(idx % (HDq / 2)); size_t t = idx / (HDq / 2);
    int n = (int)(t % NTq); int b = (int)(t / NTq);
    const float* src = (n < SPq)
        ? qkvp + ((size_t)b * SPq + n) * NQKV + (Hq * HDq)
        : qkvs + ((size_t)b * SSq + (n - SPq)) * NQKV + (Hq * HDq);
    float x1 = src[d], x2 = src[d + 128];
    float invf = powf(10000.0f, -(float)d * (1.0f / 128.0f));
    float ang = (float)n * invf;
    float cs = cosf(ang), sn = sinf(ang);
    size_t dst = ((size_t)b * NTq + n) * HDq;
    emit1(kh, kl, dst + d, x1 * cs - x2 * sn);
    emit1(kh, kl, dst + d + 128, x2 * cs + x1 * sn);
}

__global__ void transpose_v_k(const float* __restrict__ qkvp, const float* __restrict__ qkvs,
                              __nv_bfloat16* __restrict__ vh, __nv_bfloat16* __restrict__ vl)
{
    size_t idx = (size_t)blockIdx.x * blockDim.x + threadIdx.x;
    const size_t total = (size_t)Bq * NTq * HDq;
    if (idx >= total) return;
    int d = (int)(idx % HDq); size_t t = idx / HDq;
    int n = (int)(t % NTq); int b = (int)(t / NTq);
    float v = (n < SPq)
        ? qkvp[((size_t)b * SPq + n) * NQKV + (Hq * HDq + HDq) + d]
        : qkvs[((size_t)b * SSq + (n - SPq)) * NQKV + (Hq * HDq + HDq) + d];
    emit1(vh, vl, ((size_t)b * HDq + d) * NTq + n, v);
}

// ---------------- softmax (emit hi/lo) ----------------
__global__ void softmax_split_k(float* __restrict__ s, __nv_bfloat16* __restrict__ oh,
                                __nv_bfloat16* __restrict__ ol, int L)
{
    float* row = s + (size_t)blockIdx.x * L;
    __shared__ float red[256];
    float mx = -INFINITY;
    for (int c = threadIdx.x; c < L; c += 256) mx = fmaxf(mx, row[c]);
    red[threadIdx.x] = mx; __syncthreads();
    for (int st = 128; st > 0; st >>= 1) {
        if (threadIdx.x < st) red[threadIdx.x] = fmaxf(red[threadIdx.x], red[threadIdx.x + st]);
        __syncthreads();
    }
    mx = red[0]; __syncthreads();
    float sum = 0.0f;
    for (int c = threadIdx.x; c < L; c += 256) {
        float e = expf(row[c] - mx);
        row[c] = e; sum += e;
    }
    red[threadIdx.x] = sum; __syncthreads();
    for (int st = 128; st > 0; st >>= 1) {
        if (threadIdx.x < st) red[threadIdx.x] += red[threadIdx.x + st];
        __syncthreads();
    }
    float inv = 1.0f / red[0];
    size_t base = (size_t)blockIdx.x * L;
    for (int c = threadIdx.x * 2; c < L; c += 512) {
        float v0 = row[c] * inv;
        float v1 = row[c + 1] * inv;
        uint32_t hi, lo;
        split2(v0, v1, hi, lo);
        *reinterpret_cast<uint32_t*>(oh + base + c) = hi;
        *reinterpret_cast<uint32_t*>(ol + base + c) = lo;
    }
}

// ---------------- host-side dispatch ----------------
typedef __nv_bfloat16 bf16;

static void run_mm(int mode, const bf16* Ah, const bf16* Al, const bf16* Bh, const bf16* Bl,
                   float* C, int M, int N, int K,
                   long long sAz, long long sBz, int bDivB, long long sCz,
                   int Z, EpiParams ep)
{
    dim3 grid((N + 127) / 128, (M + 127) / 128, Z);
    switch (mode) {
        case 0:
            cudaFuncSetAttribute(mgemm<0>, cudaFuncAttributeMaxDynamicSharedMemorySize, MM_SMEM);
            mgemm<0><<<grid, 256, MM_SMEM>>>(Ah, Al, Bh, Bl, C, M, N, K, sAz, sBz, bDivB, sCz, ep); break;
        case 1:
            cudaFuncSetAttribute(mgemm<1>, cudaFuncAttributeMaxDynamicSharedMemorySize, MM_SMEM);
            mgemm<1><<<grid, 256, MM_SMEM>>>(Ah, Al, Bh, Bl, C, M, N, K, sAz, sBz, bDivB, sCz, ep); break;
        case 2:
            cudaFuncSetAttribute(mgemm<2>, cudaFuncAttributeMaxDynamicSharedMemorySize, MM_SMEM);
            mgemm<2><<<grid, 256, MM_SMEM>>>(Ah, Al, Bh, Bl, C, M, N, K, sAz, sBz, bDivB, sCz, ep); break;
        case 4:
            cudaFuncSetAttribute(mgemm<4>, cudaFuncAttributeMaxDynamicSharedMemorySize, MM_SMEM);
            mgemm<4><<<grid, 256, MM_SMEM>>>(Ah, Al, Bh, Bl, C, M, N, K, sAz, sBz, bDivB, sCz, ep); break;
        case 5:
            cudaFuncSetAttribute(mgemm<5>, cudaFuncAttributeMaxDynamicSharedMemorySize, MM_SMEM);
            mgemm<5><<<grid, 256, MM_SMEM>>>(Ah, Al, Bh, Bl, C, M, N, K, sAz, sBz, bDivB, sCz, ep); break;
        case 7:
            cudaFuncSetAttribute(mgemm<7>, cudaFuncAttributeMaxDynamicSharedMemorySize, MM_SMEM);
            mgemm<7><<<grid, 256, MM_SMEM>>>(Ah, Al, Bh, Bl, C, M, N, K, sAz, sBz, bDivB, sCz, ep); break;
    }
}

static void do_split(const float* s, bf16* h, bf16* l, size_t n)
{
    int blocks = (int)((n / 4 + 255) / 256);
    split_arr<<<blocks, 256>>>(s, h, l, n);
}
static void do_split_ilv(const float* s, bf16* h, bf16* l, size_t n, int K, int which)
{
    int blocks = (int)((n / 4 + 255) / 256);
    split_ilv<<<blocks, 256>>>(s, h, l, n, K, which);
}

extern "C" void kernel_launch(void* const* d_in, const int* in_sizes, int n_in,
                              void* d_out, int out_size)
{
    const float* prefix_x    = (const float*)d_in[0];
    const float* suffix_x    = (const float*)d_in[1];
    const float* cond        = (const float*)d_in[2];
    const float* p_ln_w      = (const float*)d_in[3];
    const float* p_q_w       = (const float*)d_in[4];
    const float* p_k_w       = (const float*)d_in[5];
    const float* p_v_w       = (const float*)d_in[6];
    const float* p_o_w       = (const float*)d_in[7];
    const float* p_post_ln_w = (const float*)d_in[8];
    const float* p_gate_w    = (const float*)d_in[9];
    const float* p_up_w      = (const float*)d_in[10];
    const float* p_down_w    = (const float*)d_in[11];
    const float* s_ada1_w    = (const float*)d_in[12];
    const float* s_ada1_b    = (const float*)d_in[13];
    const float* s_q_w       = (const float*)d_in[14];
    const float* s_k_w       = (const float*)d_in[15];
    const float* s_v_w       = (const float*)d_in[16];
    const float* s_o_w       = (const float*)d_in[17];
    const float* s_ada2_w    = (const float*)d_in[18];
    const float* s_ada2_b    = (const float*)d_in[19];
    const float* s_gate_w    = (const float*)d_in[20];
    const float* s_up_w      = (const float*)d_in[21];
    const float* s_down_w    = (const float*)d_in[22];

    float* scr = nullptr;
    cudaGetSymbolAddress((void**)&scr, g_scr);
    bf16* sh = nullptr;
    cudaGetSymbolAddress((void**)&sh, g_scrh);
    bf16* sl = sh + SET_TOTAL;

    float* mod1  = scr + O_MOD1;
    float* mod2  = scr + O_MOD2;
    float* qkvp  = scr + O_QKVP;
    float* qkvs  = scr + O_QKVS;
    float* sc    = scr + O_SCF;
    float* res_p = scr + O_RESP;
    float* res_s = scr + O_RESS;

    float* outp = (float*)d_out;
    float* outs = outp + NPROW * DPq;

    EpiParams ep0 = {};

    // 0) weight splits (QKV contiguous; gate/up row-interleaved)
    do_split(p_q_w,    sh + B_WPQ, sl + B_WPQ, (size_t)(Hq*HDq)*DPq);
    do_split(p_k_w,    sh + B_WPK, sl + B_WPK, (size_t)HDq*DPq);
    do_split(p_v_w,    sh + B_WPV, sl + B_WPV, (size_t)HDq*DPq);
    do_split(p_o_w,    sh + B_WPO, sl + B_WPO, (size_t)DPq*(Hq*HDq));
    do_split_ilv(p_gate_w, sh + B_WGU, sl + B_WGU, (size_t)FPq*DPq, DPq, 0);
    do_split_ilv(p_up_w,   sh + B_WGU, sl + B_WGU, (size_t)FPq*DPq, DPq, 1);
    do_split(p_down_w, sh + B_WPD, sl + B_WPD, (size_t)DPq*FPq);
    do_split(s_q_w,    sh + B_WSQ, sl + B_WSQ, (size_t)(Hq*HDq)*DSq);
    do_split(s_k_w,    sh + B_WSK, sl + B_WSK, (size_t)HDq*DSq);
    do_split(s_v_w,    sh + B_WSV, sl + B_WSV, (size_t)HDq*DSq);
    do_split(s_o_w,    sh + B_WSO, sl + B_WSO, (size_t)DSq*(Hq*HDq));
    do_split_ilv(s_gate_w, sh + B_WSGU, sl + B_WSGU, (size_t)FSq*DSq, DSq, 0);
    do_split_ilv(s_up_w,   sh + B_WSGU, sl + B_WSGU, (size_t)FSq*DSq, DSq, 1);
    do_split(s_down_w, sh + B_WSD, sl + B_WSD, (size_t)DSq*FSq);

    // 1) norms + ada modulation
    rmsnorm_split_k<<<(int)NPROW, 256>>>(prefix_x, p_ln_w, sh + B_HP, sl + B_HP, DPq);
    gemm_bias<<<dim3(24, 1, 1), 256>>>(cond, s_ada1_w, s_ada1_b, mod1, Bq, 3 * DSq, DCq);
    ada_norm_split_k<<<(int)NSROW, 256>>>(suffix_x, mod1, sh + B_HS, sl + B_HS, DSq, SSq);

    // 2) fused QKV projections
    run_mm(0, sh + B_HP, sl + B_HP, sh + B_WPQ, sl + B_WPQ, qkvp, (int)NPROW, NQKV, DPq, 0, 0, 1, 0, 1, ep0);
    run_mm(0, sh + B_HS, sl + B_HS, sh + B_WSQ, sl + B_WSQ, qkvs, (int)NSROW, NQKV, DSq, 0, 0, 1, 0, 1, ep0);

    // 3) RoPE + layouts
    {
        size_t tq = (size_t)Bq * NTq * Hq * (HDq / 2);
        rope_q_k<<<(int)((tq + 255) / 256), 256>>>(qkvp, qkvs, sh + B_Q, sl + B_Q);
        size_t tk = (size_t)Bq * NTq * (HDq / 2);
        rope_k_k<<<(int)((tk + 255) / 256), 256>>>(qkvp, qkvs, sh + B_K, sl + B_K);
        size_t tv = (size_t)Bq * NTq * HDq;
        transpose_v_k<<<(int)((tv + 255) / 256), 256>>>(qkvp, qkvs, sh + B_VT, sl + B_VT);
    }

    // 4) attention
    { EpiParams e = ep0; e.scale = 0.0625f;
      run_mm(1, sh + B_Q, sl + B_Q, sh + B_K, sl + B_K, sc, NTq, NTq, HDq,
             (long long)NTq * HDq, (long long)NTq * HDq, Hq,
             (long long)NTq * NTq, Bq * Hq, e); }
    softmax_split_k<<<Bq * Hq * NTq, 256>>>(sc, sh + B_SC, sl + B_SC, NTq);
    { EpiParams e = ep0; e.h0 = sh + B_AP; e.l0 = sl + B_AP; e.h1 = sh + B_AS; e.l1 = sl + B_AS;
      run_mm(2, sh + B_SC, sl + B_SC, sh + B_VT, sl + B_VT, nullptr, NTq, HDq, NTq,
             (long long)NTq * NTq, (long long)HDq * NTq, Hq, 0, Bq * Hq, e); }

    // 5) prefix: o-proj + residual, post-norm, fused gate/up MLP, down
    { EpiParams e = ep0; e.resid = prefix_x;
      run_mm(4, sh + B_AP, sl + B_AP, sh + B_WPO, sl + B_WPO, res_p, (int)NPROW, DPq, Hq * HDq, 0, 0, 1, 0, 1, e); }
    rmsnorm_split_k<<<(int)NPROW, 256>>>(res_p, p_post_ln_w, sh + B_HP2, sl + B_HP2, DPq);
    { EpiParams e = ep0; e.h0 = sh + B_HPM; e.l0 = sl + B_HPM;
      run_mm(7, sh + B_HP2, sl + B_HP2, sh + B_WGU, sl + B_WGU, nullptr, (int)NPROW, 2 * FPq, DPq, 0, 0, 1, 0, 1, e); }
    { EpiParams e = ep0; e.resid = res_p;
      run_mm(4, sh + B_HPM, sl + B_HPM, sh + B_WPD, sl + B_WPD, outp, (int)NPROW, DPq, FPq, 0, 0, 1, 0, 1, e); }

    // 6) suffix: gated o-proj + residual, ada-norm2, fused gate/up MLP, gated down
    { EpiParams e = ep0; e.resid = suffix_x; e.gate = mod1 + 2 * DSq; e.ldg = 3 * DSq; e.rpb = SSq;
      run_mm(5, sh + B_AS, sl + B_AS, sh + B_WSO, sl + B_WSO, res_s, (int)NSROW, DSq, Hq * HDq, 0, 0, 1, 0, 1, e); }
    gemm_bias<<<dim3(24, 1, 1), 256>>>(cond, s_ada2_w, s_ada2_b, mod2, Bq, 3 * DSq, DCq);
    ada_norm_split_k<<<(int)NSROW, 256>>>(res_s, mod2, sh + B_H2S, sl + B_H2S, DSq, SSq);
    { EpiParams e = ep0; e.h0 = sh + B_HSM; e.l0 = sl + B_HSM;
      run_mm(7, sh + B_H2S, sl + B_H2S, sh + B_WSGU, sl + B_WSGU, nullptr, (int)NSROW, 2 * FSq, DSq, 0, 0, 1, 0, 1, e); }
    { EpiParams e = ep0; e.resid = res_s; e.gate = mod2 + 2 * DSq; e.ldg = 3 * DSq; e.rpb = SSq;
      run_mm(5, sh + B_HSM, sl + B_HSM, sh + B_WSD, sl + B_WSD, outs, (int)NSROW, DSq, FSq, 0, 0, 1, 0, 1, e); }
}

// round 15
// speedup vs baseline: 1.0779x; 1.0066x over previous
#include <cuda_runtime.h>
#include <cuda_bf16.h>
#include <math.h>
#include <stdint.h>

// ---------------- problem constants ----------------
#define Bq   8
#define SPq  800
#define SSq  48
#define NTq  848
#define DPq  2048
#define DSq  1024
#define DCq  1024
#define Hq   8
#define HDq  256
#define FPq  16384
#define FSq  4096
#define EPSq 1e-6f
#define MASKV (-2.3819763e+38f)
#define NQKV 2560                 // fused QKV output cols

static constexpr size_t NPROW = (size_t)Bq * SPq;   // 6400
static constexpr size_t NSROW = (size_t)Bq * SSq;   // 384

// ---------------- f32 scratch ----------------
static constexpr size_t O_MOD1 = 0;
static constexpr size_t O_MOD2 = O_MOD1 + (size_t)Bq * 3 * DSq;
static constexpr size_t O_QKVP = O_MOD2 + (size_t)Bq * 3 * DSq;           // [6400,2560]
static constexpr size_t O_QKVS = O_QKVP + NPROW * (size_t)NQKV;           // [384,2560]
static constexpr size_t O_SCF  = O_QKVS + NSROW * (size_t)NQKV;           // scores f32
static constexpr size_t O_RESP = O_SCF  + (size_t)Bq*Hq*NTq*NTq;
static constexpr size_t O_RESS = O_RESP + NPROW * DPq;
static constexpr size_t F32_TOTAL = O_RESS + NSROW * DSq;

__device__ float g_scr[F32_TOTAL];

// ---------------- bf16 scratch (hi set + lo set) ----------------
static constexpr size_t B_HP   = 0;
static constexpr size_t B_HS   = B_HP  + NPROW * DPq;
static constexpr size_t B_Q    = B_HS  + NSROW * DSq;
static constexpr size_t B_K    = B_Q   + (size_t)Bq*Hq*NTq*HDq;
static constexpr size_t B_VT   = B_K   + (size_t)Bq*NTq*HDq;
static constexpr size_t B_SC   = B_VT  + (size_t)Bq*NTq*HDq;
static constexpr size_t B_AP   = B_SC  + (size_t)Bq*Hq*NTq*NTq;
static constexpr size_t B_AS   = B_AP  + NPROW * (size_t)(Hq*HDq);
static constexpr size_t B_HP2  = B_AS  + NSROW * (size_t)(Hq*HDq);
static constexpr size_t B_HPM  = B_HP2 + NPROW * DPq;
static constexpr size_t B_H2S  = B_HPM + NPROW * FPq;
static constexpr size_t B_HSM  = B_H2S + NSROW * DSq;
static constexpr size_t B_WPQ  = B_HSM + NSROW * FSq;                     // Wq|Wk|Wv contiguous
static constexpr size_t B_WPK  = B_WPQ + (size_t)(Hq*HDq)*DPq;
static constexpr size_t B_WPV  = B_WPK + (size_t)HDq*DPq;
static constexpr size_t B_WPO  = B_WPV + (size_t)HDq*DPq;
static constexpr size_t B_WGU  = B_WPO + (size_t)DPq*(Hq*HDq);            // interleaved gate/up [2*FP, DP]
static constexpr size_t B_WPD  = B_WGU + 2*(size_t)FPq*DPq;
static constexpr size_t B_WSQ  = B_WPD + (size_t)DPq*FPq;                 // Wq|Wk|Wv contiguous
static constexpr size_t B_WSK  = B_WSQ + (size_t)(Hq*HDq)*DSq;
static constexpr size_t B_WSV  = B_WSK + (size_t)HDq*DSq;
static constexpr size_t B_WSO  = B_WSV + (size_t)HDq*DSq;
static constexpr size_t B_WSGU = B_WSO + (size_t)DSq*(Hq*HDq);            // interleaved [2*FS, DS]
static constexpr size_t B_WSD  = B_WSGU + 2*(size_t)FSq*DSq;
static constexpr size_t SET_TOTAL = B_WSD + (size_t)DSq*FSq;

__device__ __nv_bfloat16 g_scrh[2 * SET_TOTAL];

// ---------------- helpers ----------------
__device__ __forceinline__ uint32_t smem_u32(const void* p) {
    uint32_t a;
    asm("{ .reg .u64 t; cvta.to.shared.u64 t, %1; cvt.u32.u64 %0, t; }" : "=r"(a) : "l"(p));
    return a;
}
#define LDM_X4(R, addr) \
    asm volatile("ldmatrix.sync.aligned.m8n8.x4.shared.b16 {%0,%1,%2,%3}, [%4];" \
        : "=r"((R)[0]), "=r"((R)[1]), "=r"((R)[2]), "=r"((R)[3]) : "r"(addr))
#define CP_A16(dst, src, sz) \
    asm volatile("cp.async.cg.shared.global [%0], [%1], 16, %2;" \
        :: "r"(dst), "l"(src), "r"(sz) : "memory")
#define CP_COMMIT() asm volatile("cp.async.commit_group;" ::: "memory")
#define CP_WAIT1()  asm volatile("cp.async.wait_group 1;" ::: "memory")

__device__ __forceinline__ float gelu_tanh(float x) {
    float x3 = x * x * x;
    return 0.5f * x * (1.0f + tanhf(0.7978845608028654f * (x + 0.044715f * x3)));
}
__device__ __forceinline__ void split2(float x, float y, uint32_t& hi, uint32_t& lo) {
    __nv_bfloat16 hx = __float2bfloat16_rn(x);
    __nv_bfloat16 hy = __float2bfloat16_rn(y);
    float rx = x - __bfloat162float(hx);
    float ry = y - __bfloat162float(hy);
    __nv_bfloat16 lx = __float2bfloat16_rn(rx);
    __nv_bfloat16 ly = __float2bfloat16_rn(ry);
    hi = (uint32_t)__bfloat16_as_ushort(hx) | ((uint32_t)__bfloat16_as_ushort(hy) << 16);
    lo = (uint32_t)__bfloat16_as_ushort(lx) | ((uint32_t)__bfloat16_as_ushort(ly) << 16);
}
__device__ __forceinline__ void emit1(__nv_bfloat16* h, __nv_bfloat16* l, size_t off, float v) {
    __nv_bfloat16 hv = __float2bfloat16_rn(v);
    h[off] = hv;
    l[off] = __float2bfloat16_rn(v - __bfloat162float(hv));
}

#define MMA_BF16(d, a, b) \
    asm volatile("mma.sync.aligned.m16n8k16.row.col.f32.bf16.bf16.f32 " \
        "{%0,%1,%2,%3}, {%4,%5,%6,%7}, {%8,%9}, {%0,%1,%2,%3};" \
        : "+f"((d)[0]), "+f"((d)[1]), "+f"((d)[2]), "+f"((d)[3]) \
        : "r"((a)[0]), "r"((a)[1]), "r"((a)[2]), "r"((a)[3]), "r"((b)[0]), "r"((b)[1]))

struct EpiParams {
    const float* resid;
    const float* gate;
    __nv_bfloat16 *h0, *l0, *h1, *l1;
    float scale;
    int ldg;
    int rpb;
};

// ---------------- bf16x3 NT GEMM, 2-stage cp.async ring, 2 CTAs/SM ----------
// Panel-swizzled CTA->tile map: panels of G n-tiles, m fastest within panel,
// so one wave's B working set is G*128 rows (L2-resident) instead of all N.
#define SROW 80
#define SUB  (128 * SROW)            // 10240
#define OFF_AH 0
#define OFF_AL (1 * SUB)
#define OFF_BH (2 * SUB)
#define OFF_BL (3 * SUB)
#define SLOT   (4 * SUB)             // 40960
#define MM_SMEM (2 * SLOT)           // 81920 -> 2 CTAs/SM
#define PANEL_G 16

// Modes: 0 plain f32; 1 scale+mask f32; 2 PV scatter hi/lo; 4 +resid f32;
//        5 resid+acc*gate f32; 7 interleaved gelu(gate)*up -> hi/lo (out N/2)
template <int MODE>
__global__ void __launch_bounds__(256, 2) mgemm(
    const __nv_bfloat16* __restrict__ AgH, const __nv_bfloat16* __restrict__ AgL,
    const __nv_bfloat16* __restrict__ BgH, const __nv_bfloat16* __restrict__ BgL,
    float* __restrict__ Cg, int M, int N, int K,
    long long sAz, long long sBz, int bDivB, long long sCz, EpiParams ep)
{
    extern __shared__ char smem_raw[];
    uint32_t sbase = smem_u32(smem_raw);

    int tid = threadIdx.x;
    int wid = tid >> 5, lane = tid & 31;
    int g = lane >> 2, t4 = lane & 3;
    int wm = wid & 3, wn = wid >> 2;
    int z = blockIdx.z;
    const __nv_bfloat16* Ah = AgH + (size_t)z * (size_t)sAz;
    const __nv_bfloat16* Al = AgL + (size_t)z * (size_t)sAz;
    const __nv_bfloat16* Bh = BgH + (size_t)(z / bDivB) * (size_t)sBz;
    const __nv_bfloat16* Bl = BgL + (size_t)(z / bDivB) * (size_t)sBz;

    // ---- panel swizzle (bijective remap of (blockIdx.x, blockIdx.y)) ----
    int Nx = (int)gridDim.x, My = (int)gridDim.y;
    int l = (int)blockIdx.y * Nx + (int)blockIdx.x;
    int F = Nx / PANEL_G;
    int fullCnt = F * PANEL_G * My;
    int mIdx, nIdx;
    if (l < fullCnt) {
        int p = l / (PANEL_G * My);
        int r = l - p * (PANEL_G * My);
        int mi = r / PANEL_G;
        mIdx = mi;
        nIdx = p * PANEL_G + (r - mi * PANEL_G);
    } else {
        int l2 = l - fullCnt;
        int Gp = Nx - F * PANEL_G;
        int mi = l2 / Gp;
        mIdx = mi;
        nIdx = F * PANEL_G + (l2 - mi * Gp);
    }
    int m0 = mIdx * 128;
    int n0 = nIdx * 128;

    uint32_t aoff = (uint32_t)((wm * 32 + (lane & 15)) * SROW + (lane >> 4) * 16);
    uint32_t boff = (uint32_t)((wn * 64 + ((lane & 7) | ((lane >> 4) << 3))) * SROW
                               + ((lane >> 3) & 1) * 16);

    float acc[2][8][4];
#pragma unroll
    for (int a = 0; a < 2; a++)
#pragma unroll
        for (int b = 0; b < 8; b++)
#pragma unroll
            for (int c = 0; c < 4; c++) acc[a][b][c] = 0.0f;

    int nc = (K + 31) / 32;

    auto issue = [&](int c) {
        uint32_t sb = sbase + (c & 1) * SLOT;
        int k0 = c * 32;
#pragma unroll
        for (int it = 0; it < 2; ++it) {
            int ci = it * 256 + tid;
            int row = ci >> 2, cq = ci & 3;
            int kk = k0 + cq * 8;
            bool kv = kk < K;
            uint32_t dst = sb + (uint32_t)(row * SROW + cq * 16);
            int gr = m0 + row;
            bool okA = kv && (gr < M);
            const __nv_bfloat16* sA = okA ? (Ah + (size_t)gr * K + kk) : Ah;
            const __nv_bfloat16* sAl = okA ? (Al + (size_t)gr * K + kk) : Al;
            CP_A16(dst + OFF_AH, sA, okA ? 16 : 0);
            CP_A16(dst + OFF_AL, sAl, okA ? 16 : 0);
            int gn = n0 + row;
            bool okB = kv && (gn < N);
            const __nv_bfloat16* sB = okB ? (Bh + (size_t)gn * K + kk) : Bh;
            const __nv_bfloat16* sBl = okB ? (Bl + (size_t)gn * K + kk) : Bl;
            CP_A16(dst + OFF_BH, sB, okB ? 16 : 0);
            CP_A16(dst + OFF_BL, sBl, okB ? 16 : 0);
        }
    };

    issue(0); CP_COMMIT();
    if (nc > 1) issue(1);
    CP_COMMIT();

    for (int c = 0; c < nc; ++c) {
        CP_WAIT1();
        __syncthreads();
        uint32_t sb = sbase + (c & 1) * SLOT;
#pragma unroll
        for (int kk = 0; kk < 2; ++kk) {
            uint32_t kByte = (uint32_t)(kk * 32);
            uint32_t ah[2][4], al[2][4], bb[8][2];
            LDM_X4(ah[0], sb + OFF_AH + kByte + aoff);
            LDM_X4(ah[1], sb + OFF_AH + kByte + aoff + 16 * SROW);
#pragma unroll
            for (int jp = 0; jp < 4; ++jp)
                LDM_X4(&bb[2 * jp][0], sb + OFF_BH + kByte + boff + (uint32_t)(jp * 16 * SROW));
#pragma unroll
            for (int mt = 0; mt < 2; ++mt)
#pragma unroll
                for (int j = 0; j < 8; ++j) MMA_BF16(acc[mt][j], ah[mt], bb[j]);
            LDM_X4(al[0], sb + OFF_AL + kByte + aoff);
            LDM_X4(al[1], sb + OFF_AL + kByte + aoff + 16 * SROW);
#pragma unroll
            for (int mt = 0; mt < 2; ++mt)
#pragma unroll
                for (int j = 0; j < 8; ++j) MMA_BF16(acc[mt][j], al[mt], bb[j]);
#pragma unroll
            for (int jp = 0; jp < 4; ++jp)
                LDM_X4(&bb[2 * jp][0], sb + OFF_BL + kByte + boff + (uint32_t)(jp * 16 * SROW));
#pragma unroll
            for (int mt = 0; mt < 2; ++mt)
#pragma unroll
                for (int j = 0; j < 8; ++j) MMA_BF16(acc[mt][j], ah[mt], bb[j]);
        }
        __syncthreads();
        if (c + 2 < nc) issue(c + 2);
        CP_COMMIT();
    }

    // ---------------- epilogue ----------------
#pragma unroll
    for (int mt = 0; mt < 2; ++mt) {
#pragma unroll
        for (int half = 0; half < 2; ++half) {
            int r = m0 + wm * 32 + mt * 16 + g + half * 8;
            if (r >= M) continue;
#pragma unroll
            for (int j = 0; j < 8; ++j) {
                int cc = n0 + wn * 64 + j * 8 + t4 * 2;
                if (cc >= N) continue;
                float v0 = acc[mt][j][half * 2 + 0];
                float v1 = acc[mt][j][half * 2 + 1];
                size_t idx = (size_t)r * N + cc;
                if constexpr (MODE == 0) {
                    *reinterpret_cast<float2*>(Cg + (size_t)z * sCz + idx) = make_float2(v0, v1);
                } else if constexpr (MODE == 1) {
                    float m0v = (r < SPq && cc >= SPq) ? MASKV : 0.0f;
                    float m1v = (r < SPq && cc + 1 >= SPq) ? MASKV : 0.0f;
                    *reinterpret_cast<float2*>(Cg + (size_t)z * sCz + idx) =
                        make_float2(v0 * ep.scale + m0v, v1 * ep.scale + m1v);
                } else if constexpr (MODE == 2) {
                    int b_ = z / bDivB, h_ = z % bDivB;
                    uint32_t hi, lo;
                    split2(v0, v1, hi, lo);
                    size_t off = (r < SPq)
                        ? ((size_t)b_ * SPq + r) * (Hq * HDq) + h_ * HDq + cc
                        : ((size_t)b_ * SSq + (r - SPq)) * (Hq * HDq) + h_ * HDq + cc;
                    __nv_bfloat16* dh = (r < SPq) ? ep.h0 : ep.h1;
                    __nv_bfloat16* dl = (r < SPq) ? ep.l0 : ep.l1;
                    *reinterpret_cast<uint32_t*>(dh + off) = hi;
                    *reinterpret_cast<uint32_t*>(dl + off) = lo;
                } else if constexpr (MODE == 4) {
                    float2 rs = *reinterpret_cast<const float2*>(ep.resid + idx);
                    *reinterpret_cast<float2*>(Cg + idx) = make_float2(rs.x + v0, rs.y + v1);
                } else if constexpr (MODE == 5) {
                    float2 rs = *reinterpret_cast<const float2*>(ep.resid + idx);
                    const float* gt = ep.gate + (size_t)(r / ep.rpb) * ep.ldg + cc;
                    *reinterpret_cast<float2*>(Cg + idx) =
                        make_float2(rs.x + v0 * gt[0], rs.y + v1 * gt[1]);
                } else if constexpr (MODE == 7) {
                    // interleaved: even col = gate, odd col = up; out col = cc/2
                    float gv = gelu_tanh(v0) * v1;
                    emit1(ep.h0, ep.l0, (size_t)r * (size_t)(N >> 1) + (size_t)(cc >> 1), gv);
                }
            }
        }
    }
}

// ---------------- weight split (f32 -> bf16 hi/lo) ----------------
__global__ void split_arr(const float* __restrict__ s, __nv_bfloat16* __restrict__ h,
                          __nv_bfloat16* __restrict__ l, size_t n)
{
    size_t i = ((size_t)blockIdx.x * 256 + threadIdx.x) * 4;
    if (i >= n) return;
    float4 v = *reinterpret_cast<const float4*>(s + i);
    uint32_t h0, l0, h1, l1;
    split2(v.x, v.y, h0, l0);
    split2(v.z, v.w, h1, l1);
    *reinterpret_cast<uint2*>(h + i) = make_uint2(h0, h1);
    *reinterpret_cast<uint2*>(l + i) = make_uint2(l0, l1);
}

// interleaved split: src row r -> dst row 2r+which (row-major [rows,K])
__global__ void split_ilv(const float* __restrict__ s, __nv_bfloat16* __restrict__ h,
                          __nv_bfloat16* __restrict__ l, size_t n, int K, int which)
{
    size_t i = ((size_t)blockIdx.x * 256 + threadIdx.x) * 4;
    if (i >= n) return;
    size_t r = i / (size_t)K;
    int k = (int)(i - r * (size_t)K);
    size_t o = ((r << 1) | (size_t)which) * (size_t)K + (size_t)k;
    float4 v = *reinterpret_cast<const float4*>(s + i);
    uint32_t h0, l0, h1, l1;
    split2(v.x, v.y, h0, l0);
    split2(v.z, v.w, h1, l1);
    *reinterpret_cast<uint2*>(h + o) = make_uint2(h0, h1);
    *reinterpret_cast<uint2*>(l + o) = make_uint2(l0, l1);
}

// ---------------- small SIMT GEMM for cond modulation (M=8) -----------------
__global__ void __launch_bounds__(256) gemm_bias(
    const float* __restrict__ A, const float* __restrict__ B,
    const float* __restrict__ bias, float* __restrict__ C, int M, int N, int K)
{
    __shared__ float As[8][128];
    __shared__ float Bs[8][128];
    int m0 = blockIdx.y * 128, n0 = blockIdx.x * 128;
    int tid = threadIdx.x, tx = tid & 15, ty = tid >> 4;
    int ldRow = tid >> 1, ldCol = (tid & 1) * 4;
    float acc[8][8];
#pragma unroll
    for (int i = 0; i < 8; i++)
#pragma unroll
        for (int j = 0; j < 8; j++) acc[i][j] = 0.0f;
    for (int k0 = 0; k0 < K; k0 += 8) {
        float4 av = make_float4(0.f, 0.f, 0.f, 0.f);
        if (m0 + ldRow < M) av = *reinterpret_cast<const float4*>(A + (size_t)(m0 + ldRow) * K + k0 + ldCol);
        As[ldCol + 0][ldRow] = av.x; As[ldCol + 1][ldRow] = av.y;
        As[ldCol + 2][ldRow] = av.z; As[ldCol + 3][ldRow] = av.w;
        float4 bv = make_float4(0.f, 0.f, 0.f, 0.f);
        if (n0 + ldRow < N) bv = *reinterpret_cast<const float4*>(B + (size_t)(n0 + ldRow) * K + k0 + ldCol);
        Bs[ldCol + 0][ldRow] = bv.x; Bs[ldCol + 1][ldRow] = bv.y;
        Bs[ldCol + 2][ldRow] = bv.z; Bs[ldCol + 3][ldRow] = bv.w;
        __syncthreads();
#pragma unroll
        for (int kk = 0; kk < 8; kk++) {
            float a[8], b[8];
#pragma unroll
            for (int i = 0; i < 8; i++) a[i] = As[kk][ty * 8 + i];
#pragma unroll
            for (int j = 0; j < 8; j++) b[j] = Bs[kk][tx * 8 + j];
#pragma unroll
            for (int i = 0; i < 8; i++)
#pragma unroll
                for (int j = 0; j < 8; j++) acc[i][j] += a[i] * b[j];
        }
        __syncthreads();
    }
#pragma unroll
    for (int i = 0; i < 8; i++) {
        int r = m0 + ty * 8 + i;
        if (r >= M) continue;
#pragma unroll
        for (int j = 0; j < 8; j++) {
            int c = n0 + tx * 8 + j;
            if (c >= N) continue;
            C[(size_t)r * N + c] = acc[i][j] + bias[c];
        }
    }
}

// ---------------- norms (emit bf16 hi/lo) ----------------
__global__ void rmsnorm_split_k(const float* __restrict__ x, const float* __restrict__ w,
                                __nv_bfloat16* __restrict__ oh, __nv_bfloat16* __restrict__ ol, int D)
{
    int row = blockIdx.x;
    const float* xr = x + (size_t)row * D;
    float ss = 0.0f;
    for (int c = threadIdx.x; c < D; c += 256) { float v = xr[c]; ss += v * v; }
    __shared__ float red[256];
    red[threadIdx.x] = ss; __syncthreads();
    for (int s = 128; s > 0; s >>= 1) {
        if (threadIdx.x < s) red[threadIdx.x] += red[threadIdx.x + s];
        __syncthreads();
    }
    float rinv = rsqrtf(red[0] / (float)D + EPSq);
    size_t base = (size_t)row * D;
    for (int c = threadIdx.x * 2; c < D; c += 512) {
        float v0 = xr[c] * rinv * (1.0f + w[c]);
        float v1 = xr[c + 1] * rinv * (1.0f + w[c + 1]);
        uint32_t hi, lo;
        split2(v0, v1, hi, lo);
        *reinterpret_cast<uint32_t*>(oh + base + c) = hi;
        *reinterpret_cast<uint32_t*>(ol + base + c) = lo;
    }
}

__global__ void ada_norm_split_k(const float* __restrict__ x, const float* __restrict__ mod,
                                 __nv_bfloat16* __restrict__ oh, __nv_bfloat16* __restrict__ ol,
                                 int D, int rowsPerB)
{
    int row = blockIdx.x;
    int b = row / rowsPerB;
    const float* xr = x + (size_t)row * D;
    float ss = 0.0f;
    for (int c = threadIdx.x; c < D; c += 256) { float v = xr[c]; ss += v * v; }
    __shared__ float red[256];
    red[threadIdx.x] = ss; __syncthreads();
    for (int s = 128; s > 0; s >>= 1) {
        if (threadIdx.x < s) red[threadIdx.x] += red[threadIdx.x + s];
        __syncthreads();
    }
    float rinv = rsqrtf(red[0] / (float)D + EPSq);
    const float* mb = mod + (size_t)b * 3 * D;
    size_t base = (size_t)row * D;
    for (int c = threadIdx.x * 2; c < D; c += 512) {
        float v0 = xr[c] * rinv * (1.0f + mb[c]) + mb[D + c];
        float v1 = xr[c + 1] * rinv * (1.0f + mb[c + 1]) + mb[D + c + 1];
        uint32_t hi, lo;
        split2(v0, v1, hi, lo);
        *reinterpret_cast<uint32_t*>(oh + base + c) = hi;
        *reinterpret_cast<uint32_t*>(ol + base + c) = lo;
    }
}

// ---------------- rope / transpose from fused QKV (stride 2560) -------------
__global__ void rope_q_k(const float* __restrict__ qkvp, const float* __restrict__ qkvs,
                         __nv_bfloat16* __restrict__ qh, __nv_bfloat16* __restrict__ ql)
{
    size_t idx = (size_t)blockIdx.x * blockDim.x + threadIdx.x;
    const size_t total = (size_t)Bq * NTq * Hq * (HDq / 2);
    if (idx >= total) return;
    int d = (int)(idx % (HDq / 2)); size_t t = idx / (HDq / 2);
    int h = (int)(t % Hq); t /= Hq;
    int n = (int)(t % NTq); int b = (int)(t / NTq);
    const float* src = (n < SPq)
        ? qkvp + ((size_t)b * SPq + n) * NQKV + h * HDq
        : qkvs + ((size_t)b * SSq + (n - SPq)) * NQKV + h * HDq;
    float x1 = src[d], x2 = src[d + 128];
    float invf = powf(10000.0f, -(float)d * (1.0f / 128.0f));
    float ang = (float)n * invf;
    float cs = cosf(ang), sn = sinf(ang);
    size_t dst = (((size_t)b * Hq + h) * NTq + n) * HDq;
    emit1(qh, ql, dst + d, x1 * cs - x2 * sn);
    emit1(qh, ql, dst + d + 128, x2 * cs + x1 * sn);
}

__global__ void rope_k_k(const float* __restrict__ qkvp, const float* __restrict__ qkvs,
                         __nv_bfloat16* __restrict__ kh, __nv_bfloat16* __restrict__ kl)
{
    size_t idx = (size_t)blockIdx.x * blockDim.x + threadIdx.x;
    const size_t total = (size_t)Bq * NTq * (HDq / 2);
    if (idx >= total) return;
    int d = (int)(idx % (HDq / 2)); size_t t = idx / (HDq / 2);
    int n = (int)(t % NTq); int b = (int)(t / NTq);
    const float* src = (n < SPq)
        ? qkvp + ((size_t)b * SPq + n) * NQKV + (Hq * HDq)
        : qkvs + ((size_t)b * SSq + (n - SPq)) * NQKV + (Hq * HDq);
    float x1 = src[d], x2 = src[d + 128];
    float invf = powf(10000.0f, -(float)d * (1.0f / 128.0f));
    float ang = (float)n * invf;
    float cs = cosf(ang), sn = sinf(ang);
    size_t dst = ((size_t)b * NTq + n) * HDq;
    emit1(kh, kl, dst + d, x1 * cs - x2 * sn);
    emit1(kh, kl, dst + d + 128, x2 * cs + x1 * sn);
}

__global__ void transpose_v_k(const float* __restrict__ qkvp, const float* __restrict__ qkvs,
                              __nv_bfloat16* __restrict__ vh, __nv_bfloat16* __restrict__ vl)
{
    size_t idx = (size_t)blockIdx.x * blockDim.x + threadIdx.x;
    const size_t total = (size_t)Bq * NTq * HDq;
    if (idx >= total) return;
    int d = (int)(idx % HDq); size_t t = idx / HDq;
    int n = (int)(t % NTq); int b = (int)(t / NTq);
    float v = (n < SPq)
        ? qkvp[((size_t)b * SPq + n) * NQKV + (Hq * HDq + HDq) + d]
        : qkvs[((size_t)b * SSq + (n - SPq)) * NQKV + (Hq * HDq + HDq) + d];
    emit1(vh, vl, ((size_t)b * HDq + d) * NTq + n, v);
}

// ---------------- softmax (emit hi/lo) ----------------
__global__ void softmax_split_k(float* __restrict__ s, __nv_bfloat16* __restrict__ oh,
                                __nv_bfloat16* __restrict__ ol, int L)
{
    float* row = s + (size_t)blockIdx.x * L;
    __shared__ float red[256];
    float mx = -INFINITY;
    for (int c = threadIdx.x; c < L; c += 256) mx = fmaxf(mx, row[c]);
    red[threadIdx.x] = mx; __syncthreads();
    for (int st = 128; st > 0; st >>= 1) {
        if (threadIdx.x < st) red[threadIdx.x] = fmaxf(red[threadIdx.x], red[threadIdx.x + st]);
        __syncthreads();
    }
    mx = red[0]; __syncthreads();
    float sum = 0.0f;
    for (int c = threadIdx.x; c < L; c += 256) {
        float e = expf(row[c] - mx);
        row[c] = e; sum += e;
    }
    red[threadIdx.x] = sum; __syncthreads();
    for (int st = 128; st > 0; st >>= 1) {
        if (threadIdx.x < st) red[threadIdx.x] += red[threadIdx.x + st];
        __syncthreads();
    }
    float inv = 1.0f / red[0];
    size_t base = (size_t)blockIdx.x * L;
    for (int c = threadIdx.x * 2; c < L; c += 512) {
        float v0 = row[c] * inv;
        float v1 = row[c + 1] * inv;
        uint32_t hi, lo;
        split2(v0, v1, hi, lo);
        *reinterpret_cast<uint32_t*>(oh + base + c) = hi;
        *reinterpret_cast<uint32_t*>(ol + base + c) = lo;
    }
}

// ---------------- host-side dispatch ----------------
typedef __nv_bfloat16 bf16;

static void run_mm(int mode, const bf16* Ah, const bf16* Al, const bf16* Bh, const bf16* Bl,
                   float* C, int M, int N, int K,
                   long long sAz, long long sBz, int bDivB, long long sCz,
                   int Z, EpiParams ep)
{
    dim3 grid((N + 127) / 128, (M + 127) / 128, Z);
    switch (mode) {
        case 0:
            cudaFuncSetAttribute(mgemm<0>, cudaFuncAttributeMaxDynamicSharedMemorySize, MM_SMEM);
            mgemm<0><<<grid, 256, MM_SMEM>>>(Ah, Al, Bh, Bl, C, M, N, K, sAz, sBz, bDivB, sCz, ep); break;
        case 1:
            cudaFuncSetAttribute(mgemm<1>, cudaFuncAttributeMaxDynamicSharedMemorySize, MM_SMEM);
            mgemm<1><<<grid, 256, MM_SMEM>>>(Ah, Al, Bh, Bl, C, M, N, K, sAz, sBz, bDivB, sCz, ep); break;
        case 2:
            cudaFuncSetAttribute(mgemm<2>, cudaFuncAttributeMaxDynamicSharedMemorySize, MM_SMEM);
            mgemm<2><<<grid, 256, MM_SMEM>>>(Ah, Al, Bh, Bl, C, M, N, K, sAz, sBz, bDivB, sCz, ep); break;
        case 4:
            cudaFuncSetAttribute(mgemm<4>, cudaFuncAttributeMaxDynamicSharedMemorySize, MM_SMEM);
            mgemm<4><<<grid, 256, MM_SMEM>>>(Ah, Al, Bh, Bl, C, M, N, K, sAz, sBz, bDivB, sCz, ep); break;
        case 5:
            cudaFuncSetAttribute(mgemm<5>, cudaFuncAttributeMaxDynamicSharedMemorySize, MM_SMEM);
            mgemm<5><<<grid, 256, MM_SMEM>>>(Ah, Al, Bh, Bl, C, M, N, K, sAz, sBz, bDivB, sCz, ep); break;
        case 7:
            cudaFuncSetAttribute(mgemm<7>, cudaFuncAttributeMaxDynamicSharedMemorySize, MM_SMEM);
            mgemm<7><<<grid, 256, MM_SMEM>>>(Ah, Al, Bh, Bl, C, M, N, K, sAz, sBz, bDivB, sCz, ep); break;
    }
}

static void do_split(const float* s, bf16* h, bf16* l, size_t n)
{
    int blocks = (int)((n / 4 + 255) / 256);
    split_arr<<<blocks, 256>>>(s, h, l, n);
}
static void do_split_ilv(const float* s, bf16* h, bf16* l, size_t n, int K, int which)
{
    int blocks = (int)((n / 4 + 255) / 256);
    split_ilv<<<blocks, 256>>>(s, h, l, n, K, which);
}

extern "C" void kernel_launch(void* const* d_in, const int* in_sizes, int n_in,
                              void* d_out, int out_size)
{
    const float* prefix_x    = (const float*)d_in[0];
    const float* suffix_x    = (const float*)d_in[1];
    const float* cond        = (const float*)d_in[2];
    const float* p_ln_w      = (const float*)d_in[3];
    const float* p_q_w       = (const float*)d_in[4];
    const float* p_k_w       = (const float*)d_in[5];
    const float* p_v_w       = (const float*)d_in[6];
    const float* p_o_w       = (const float*)d_in[7];
    const float* p_post_ln_w = (const float*)d_in[8];
    const float* p_gate_w    = (const float*)d_in[9];
    const float* p_up_w      = (const float*)d_in[10];
    const float* p_down_w    = (const float*)d_in[11];
    const float* s_ada1_w    = (const float*)d_in[12];
    const float* s_ada1_b    = (const float*)d_in[13];
    const float* s_q_w       = (const float*)d_in[14];
    const float* s_k_w       = (const float*)d_in[15];
    const float* s_v_w       = (const float*)d_in[16];
    const float* s_o_w       = (const float*)d_in[17];
    const float* s_ada2_w    = (const float*)d_in[18];
    const float* s_ada2_b    = (const float*)d_in[19];
    const float* s_gate_w    = (const float*)d_in[20];
    const float* s_up_w      = (const float*)d_in[21];
    const float* s_down_w    = (const float*)d_in[22];

    float* scr = nullptr;
    cudaGetSymbolAddress((void**)&scr, g_scr);
    bf16* sh = nullptr;
    cudaGetSymbolAddress((void**)&sh, g_scrh);
    bf16* sl = sh + SET_TOTAL;

    float* mod1  = scr + O_MOD1;
    float* mod2  = scr + O_MOD2;
    float* qkvp  = scr + O_QKVP;
    float* qkvs  = scr + O_QKVS;
    float* sc    = scr + O_SCF;
    float* res_p = scr + O_RESP;
    float* res_s = scr + O_RESS;

    float* outp = (float*)d_out;
    float* outs = outp + NPROW * DPq;

    EpiParams ep0 = {};

    // 0) weight splits (QKV contiguous; gate/up row-interleaved)
    do_split(p_q_w,    sh + B_WPQ, sl + B_WPQ, (size_t)(Hq*HDq)*DPq);
    do_split(p_k_w,    sh + B_WPK, sl + B_WPK, (size_t)HDq*DPq);
    do_split(p_v_w,    sh + B_WPV, sl + B_WPV, (size_t)HDq*DPq);
    do_split(p_o_w,    sh + B_WPO, sl + B_WPO, (size_t)DPq*(Hq*HDq));
    do_split_ilv(p_gate_w, sh + B_WGU, sl + B_WGU, (size_t)FPq*DPq, DPq, 0);
    do_split_ilv(p_up_w,   sh + B_WGU, sl + B_WGU, (size_t)FPq*DPq, DPq, 1);
    do_split(p_down_w, sh + B_WPD, sl + B_WPD, (size_t)DPq*FPq);
    do_split(s_q_w,    sh + B_WSQ, sl + B_WSQ, (size_t)(Hq*HDq)*DSq);
    do_split(s_k_w,    sh + B_WSK, sl + B_WSK, (size_t)HDq*DSq);
    do_split(s_v_w,    sh + B_WSV, sl + B_WSV, (size_t)HDq*DSq);
    do_split(s_o_w,    sh + B_WSO, sl + B_WSO, (size_t)DSq*(Hq*HDq));
    do_split_ilv(s_gate_w, sh + B_WSGU, sl + B_WSGU, (size_t)FSq*DSq, DSq, 0);
    do_split_ilv(s_up_w,   sh + B_WSGU, sl + B_WSGU, (size_t)FSq*DSq, DSq, 1);
    do_split(s_down_w, sh + B_WSD, sl + B_WSD, (size_t)DSq*FSq);

    // 1) norms + ada modulation
    rmsnorm_split_k<<<(int)NPROW, 256>>>(prefix_x, p_ln_w, sh + B_HP, sl + B_HP, DPq);
    gemm_bias<<<dim3(24, 1, 1), 256>>>(cond, s_ada1_w, s_ada1_b, mod1, Bq, 3 * DSq, DCq);
    ada_norm_split_k<<<(int)NSROW, 256>>>(suffix_x, mod1, sh + B_HS, sl + B_HS, DSq, SSq);

    // 2) fused QKV projections
    run_mm(0, sh + B_HP, sl + B_HP, sh + B_WPQ, sl + B_WPQ, qkvp, (int)NPROW, NQKV, DPq, 0, 0, 1, 0, 1, ep0);
    run_mm(0, sh + B_HS, sl + B_HS, sh + B_WSQ, sl + B_WSQ, qkvs, (int)NSROW, NQKV, DSq, 0, 0, 1, 0, 1, ep0);

    // 3) RoPE + layouts
    {
        size_t tq = (size_t)Bq * NTq * Hq * (HDq / 2);
        rope_q_k<<<(int)((tq + 255) / 256), 256>>>(qkvp, qkvs, sh + B_Q, sl + B_Q);
        size_t tk = (size_t)Bq * NTq * (HDq / 2);
        rope_k_k<<<(int)((tk + 255) / 256), 256>>>(qkvp, qkvs, sh + B_K, sl + B_K);
        size_t tv = (size_t)Bq * NTq * HDq;
        transpose_v_k<<<(int)((tv + 255) / 256), 256>>>(qkvp, qkvs, sh + B_VT, sl + B_VT);
    }

    // 4) attention
    { EpiParams e = ep0; e.scale = 0.0625f;
      run_mm(1, sh + B_Q, sl + B_Q, sh + B_K, sl + B_K, sc, NTq, NTq, HDq,
             (long long)NTq * HDq, (long long)NTq * HDq, Hq,
             (long long)NTq * NTq, Bq * Hq, e); }
    softmax_split_k<<<Bq * Hq * NTq, 256>>>(sc, sh + B_SC, sl + B_SC, NTq);
    { EpiParams e = ep0; e.h0 = sh + B_AP; e.l0 = sl + B_AP; e.h1 = sh + B_AS; e.l1 = sl + B_AS;
      run_mm(2, sh + B_SC, sl + B_SC, sh + B_VT, sl + B_VT, nullptr, NTq, HDq, NTq,
             (long long)NTq * NTq, (long long)HDq * NTq, Hq, 0, Bq * Hq, e); }

    // 5) prefix: o-proj + residual, post-norm, fused gate/up MLP, down
    { EpiParams e = ep0; e.resid = prefix_x;
      run_mm(4, sh + B_AP, sl + B_AP, sh + B_WPO, sl + B_WPO, res_p, (int)NPROW, DPq, Hq * HDq, 0, 0, 1, 0, 1, e); }
    rmsnorm_split_k<<<(int)NPROW, 256>>>(res_p, p_post_ln_w, sh + B_HP2, sl + B_HP2, DPq);
    { EpiParams e = ep0; e.h0 = sh + B_HPM; e.l0 = sl + B_HPM;
      run_mm(7, sh + B_HP2, sl + B_HP2, sh + B_WGU, sl + B_WGU, nullptr, (int)NPROW, 2 * FPq, DPq, 0, 0, 1, 0, 1, e); }
    { EpiParams e = ep0; e.resid = res_p;
      run_mm(4, sh + B_HPM, sl + B_HPM, sh + B_WPD, sl + B_WPD, outp, (int)NPROW, DPq, FPq, 0, 0, 1, 0, 1, e); }

    // 6) suffix: gated o-proj + residual, ada-norm2, fused gate/up MLP, gated down
    { EpiParams e = ep0; e.resid = suffix_x; e.gate = mod1 + 2 * DSq; e.ldg = 3 * DSq; e.rpb = SSq;
      run_mm(5, sh + B_AS, sl + B_AS, sh + B_WSO, sl + B_WSO, res_s, (int)NSROW, DSq, Hq * HDq, 0, 0, 1, 0, 1, e); }
    gemm_bias<<<dim3(24, 1, 1), 256>>>(cond, s_ada2_w, s_ada2_b, mod2, Bq, 3 * DSq, DCq);
    ada_norm_split_k<<<(int)NSROW, 256>>>(res_s, mod2, sh + B_H2S, sl + B_H2S, DSq, SSq);
    { EpiParams e = ep0; e.h0 = sh + B_HSM; e.l0 = sl + B_HSM;
      run_mm(7, sh + B_H2S, sl + B_H2S, sh + B_WSGU, sl + B_WSGU, nullptr, (int)NSROW, 2 * FSq, DSq, 0, 0, 1, 0, 1, e); }
    { EpiParams e = ep0; e.resid = res_s; e.gate = mod2 + 2 * DSq; e.ldg = 3 * DSq; e.rpb = SSq;
      run_mm(5, sh + B_HSM, sl + B_HSM, sh + B_WSD, sl + B_WSD, outs, (int)NSROW, DSq, FSq, 0, 0, 1, 0, 1, e); }
}